// round 12
// baseline (speedup 1.0000x reference)
#include <cuda_runtime.h>
#include <stdint.h>
#include <math.h>

// Problem constants
#define BB  4
#define TT  1024
#define DD  768
#define NCH 7
#define BT  (BB*TT)   // 4096 rows

// ---------------------------------------------------------------------------
// Scratch (device globals; no allocation allowed in kernel_launch)
// ---------------------------------------------------------------------------
__device__ float g_h   [(size_t)BT*DD];
__device__ float g_in  [(size_t)BT*DD];
__device__ float g_seq [(size_t)BT*DD];
__device__ float g_par [(size_t)BT*DD];
// parallel branch (chambers 1..6 use slots 1..6; slot 0 unused)
__device__ float g_q   [(size_t)NCH*BT*DD];
__device__ float g_k   [(size_t)NCH*BT*DD];
__device__ float g_o   [(size_t)NCH*BT*DD];
__device__ float g_d   [(size_t)NCH*BT*DD];
__device__ float g_S   [(size_t)NCH*BB*TT*TT];
// sequential-branch private buffers
__device__ float g_qk2 [(size_t)2*BT*DD];      // fused Q|K output
__device__ float g_o2  [(size_t)BT*DD];
__device__ float g_S2  [(size_t)BB*TT*TT];
// TF32-rounded weights: interleaved [chamber][q|k][D][D], plus merge
__device__ float g_wqk [(size_t)NCH*2*DD*DD];
__device__ float g_mw  [(size_t)DD*NCH*DD];

// ---------------------------------------------------------------------------
// TF32 helpers
// ---------------------------------------------------------------------------
__device__ __forceinline__ uint32_t f2tf(float f) {
    uint32_t r;
    asm("cvt.rna.tf32.f32 %0, %1;" : "=r"(r) : "f"(f));
    return r;
}
__device__ __forceinline__ float tf32r(float f) { return __uint_as_float(f2tf(f)); }

__device__ __forceinline__ void mma_tf32(float c[4],
    uint32_t a0, uint32_t a1, uint32_t a2, uint32_t a3,
    uint32_t b0, uint32_t b1)
{
    asm volatile(
        "mma.sync.aligned.m16n8k8.row.col.f32.tf32.tf32.f32 "
        "{%0,%1,%2,%3}, {%4,%5,%6,%7}, {%8,%9}, {%0,%1,%2,%3};"
        : "+f"(c[0]), "+f"(c[1]), "+f"(c[2]), "+f"(c[3])
        : "r"(a0), "r"(a1), "r"(a2), "r"(a3), "r"(b0), "r"(b1));
}
#define CPA16(saddr, gptr) \
    asm volatile("cp.async.cg.shared.global [%0], [%1], 16;" :: "r"(saddr), "l"(gptr))
#define CPA_COMMIT() asm volatile("cp.async.commit_group;")
#define CPA_WAIT2()  asm volatile("cp.async.wait_group 2;")

// ---------------------------------------------------------------------------
// TF32 MMA GEMM, 4-stage cp.async pipeline, dynamic smem.
// C = round_tf32( alpha * A @ op(B) (+ C if ACC) )
// Operands must already be TF32-rounded (producers round at write).
//   A: M x K row-major (lda). kchunk>0: K-concat of chunks (merge GEMM).
//   B: TRANSB ? N x K row-major : K x N row-major. bmod>0 -> B uses z%bmod.
//   CSKIP: skip C tiles fully above diagonal. CKLIM: cap K at tile diagonal.
// Tiles 128x128x16, 8 warps, 64x32 warp tile.
// ---------------------------------------------------------------------------
#define ASTRIDE 20
#define BSTRIDE 136
#define AS_SZ  (128*ASTRIDE)
#define STG_SZ (2*AS_SZ)          // 5120 floats = 20 KB per stage
#define NSTG   4
#define GEMM_SMEM (NSTG*STG_SZ*(int)sizeof(float))   // 81920 B

template<bool TRANSB, bool ACC, bool CSKIP, bool CKLIM>
__global__ void __launch_bounds__(256, 2)
mma_gemm(const float* __restrict__ A, int lda, long long sA,
         const float* __restrict__ Bp, int ldb, long long sB, int bmod,
         float* __restrict__ C, int ldc, long long sC,
         int M, int N, int K, float alpha,
         int kchunk, long long schunk)
{
    extern __shared__ float smdyn[];

    const int m0 = blockIdx.y * 128;
    const int n0 = blockIdx.x * 128;
    if (CSKIP && n0 > m0 + 127) return;

    const int z = blockIdx.z;
    A  += (long long)z * sA;
    Bp += (long long)(bmod ? (z % bmod) : z) * sB;
    C  += (long long)z * sC;

    int kend = K;
    if (CKLIM) { int ke = m0 + 128; kend = (ke < K) ? ke : K; }
    const int niter = kend >> 4;   // always >= 8 here

    const int tid  = threadIdx.x;
    const int wid  = tid >> 5;
    const int lane = tid & 31;
    const int gid  = lane >> 2;
    const int tig  = lane & 3;
    const int wm   = (wid & 1) * 64;
    const int wn   = (wid >> 1) * 32;

    float acc[4][4][4];
    #pragma unroll
    for (int i = 0; i < 4; i++)
        #pragma unroll
        for (int j = 0; j < 4; j++)
            #pragma unroll
            for (int r = 0; r < 4; r++) acc[i][j][r] = 0.f;

    auto loadA = [&](int stg, int k0) {
        const float* Ab;
        if (kchunk) { int c = k0 / kchunk; Ab = A + (long long)c * schunk + (k0 - c * kchunk); }
        else        Ab = A + k0;
        float* as = smdyn + stg * STG_SZ;
        #pragma unroll
        for (int i = 0; i < 2; i++) {
            int idx = tid + i * 256;
            int r = idx >> 2, c4 = (idx & 3) << 2;
            uint32_t sa = (uint32_t)__cvta_generic_to_shared(&as[r * ASTRIDE + c4]);
            CPA16(sa, Ab + (long long)(m0 + r) * lda + c4);
        }
    };
    auto loadB = [&](int stg, int k0) {
        float* bs = smdyn + stg * STG_SZ + AS_SZ;
        if (TRANSB) {
            #pragma unroll
            for (int i = 0; i < 2; i++) {
                int idx = tid + i * 256;
                int r = idx >> 2, c4 = (idx & 3) << 2;
                uint32_t sa = (uint32_t)__cvta_generic_to_shared(&bs[r * ASTRIDE + c4]);
                CPA16(sa, Bp + (long long)(n0 + r) * ldb + k0 + c4);
            }
        } else {
            #pragma unroll
            for (int i = 0; i < 2; i++) {
                int idx = tid + i * 256;
                int r = idx >> 5, c4 = (idx & 31) << 2;
                uint32_t sa = (uint32_t)__cvta_generic_to_shared(&bs[r * BSTRIDE + c4]);
                CPA16(sa, Bp + (long long)(k0 + r) * ldb + n0 + c4);
            }
        }
    };

    // prologue: stages 0,1,2 (niter >= 8 always)
    loadA(0, 0);       loadB(0, 0);       CPA_COMMIT();
    loadA(1, 1 << 4);  loadB(1, 1 << 4);  CPA_COMMIT();
    loadA(2, 2 << 4);  loadB(2, 2 << 4);  CPA_COMMIT();

    for (int it = 0; it < niter; ++it) {
        CPA_WAIT2();            // group 'it' complete; it+1, it+2 may be in flight
        __syncthreads();        // all threads done computing stage (it-1)&3
        const int ld = it + 3;  // refill buffer (it-1)&3
        if (ld < niter) { loadA(ld & 3, ld << 4); loadB(ld & 3, ld << 4); }
        CPA_COMMIT();           // commit (possibly empty) to keep group accounting uniform

        const float* as = smdyn + (it & 3) * STG_SZ;
        const float* bs = as + AS_SZ;

        #pragma unroll
        for (int kk = 0; kk < 16; kk += 8) {
            uint32_t a[4][4];
            #pragma unroll
            for (int mi = 0; mi < 4; mi++) {
                int mb = wm + mi * 16 + gid;
                a[mi][0] = __float_as_uint(as[ mb      * ASTRIDE + kk + tig    ]);
                a[mi][1] = __float_as_uint(as[(mb + 8) * ASTRIDE + kk + tig    ]);
                a[mi][2] = __float_as_uint(as[ mb      * ASTRIDE + kk + tig + 4]);
                a[mi][3] = __float_as_uint(as[(mb + 8) * ASTRIDE + kk + tig + 4]);
            }
            uint32_t b[4][2];
            #pragma unroll
            for (int ni = 0; ni < 4; ni++) {
                int nb = wn + ni * 8 + gid;
                if (TRANSB) {
                    b[ni][0] = __float_as_uint(bs[nb * ASTRIDE + kk + tig    ]);
                    b[ni][1] = __float_as_uint(bs[nb * ASTRIDE + kk + tig + 4]);
                } else {
                    b[ni][0] = __float_as_uint(bs[(kk + tig    ) * BSTRIDE + nb]);
                    b[ni][1] = __float_as_uint(bs[(kk + tig + 4) * BSTRIDE + nb]);
                }
            }
            #pragma unroll
            for (int mi = 0; mi < 4; mi++)
                #pragma unroll
                for (int ni = 0; ni < 4; ni++)
                    mma_tf32(acc[mi][ni], a[mi][0], a[mi][1], a[mi][2], a[mi][3],
                             b[ni][0], b[ni][1]);
        }
    }

    // epilogue — TF32-rounded so downstream GEMMs skip cvt
    #pragma unroll
    for (int mi = 0; mi < 4; mi++) {
        #pragma unroll
        for (int ni = 0; ni < 4; ni++) {
            const int rr = m0 + wm + mi * 16 + gid;
            const int cc = n0 + wn + ni * 8 + tig * 2;
            #pragma unroll
            for (int hh = 0; hh < 2; hh++) {
                long long idx = (long long)(rr + hh * 8) * ldc + cc;
                float2 v;
                v.x = alpha * acc[mi][ni][hh * 2 + 0];
                v.y = alpha * acc[mi][ni][hh * 2 + 1];
                if (ACC) {
                    float2 c = *reinterpret_cast<const float2*>(&C[idx]);
                    v.x += c.x; v.y += c.y;
                }
                v.x = tf32r(v.x);
                v.y = tf32r(v.y);
                *reinterpret_cast<float2*>(&C[idx]) = v;
            }
        }
    }
}

// ---------------------------------------------------------------------------
// Weight rounding kernels
// ---------------------------------------------------------------------------
__global__ void round_tf32_kernel(const float* __restrict__ in,
                                  float* __restrict__ out, int n4)
{
    int i = blockIdx.x * 256 + threadIdx.x;
    if (i < n4) {
        float4 v = reinterpret_cast<const float4*>(in)[i];
        v.x = tf32r(v.x); v.y = tf32r(v.y); v.z = tf32r(v.z); v.w = tf32r(v.w);
        reinterpret_cast<float4*>(out)[i] = v;
    }
}

// Round + interleave into wqk[(2*chamber+which)*D*D + rem]
__global__ void round_inter_kernel(const float* __restrict__ in,
                                   float* __restrict__ out, int which, int n4)
{
    const int q4 = DD * DD / 4;
    int i = blockIdx.x * 256 + threadIdx.x;
    if (i < n4) {
        int c = i / q4, rem = i - c * q4;
        float4 v = reinterpret_cast<const float4*>(in)[i];
        v.x = tf32r(v.x); v.y = tf32r(v.y); v.z = tf32r(v.z); v.w = tf32r(v.w);
        reinterpret_cast<float4*>(out)[(2 * c + which) * q4 + rem] = v;
    }
}

// ---------------------------------------------------------------------------
// Causal softmax in place (rows of [nz][T][T]); TF32-rounded, zero-filled
// to the 128 tile boundary.
// ---------------------------------------------------------------------------
__global__ void __launch_bounds__(256)
softmax_causal_kernel(float* __restrict__ S)
{
    __shared__ float red[256];
    const int r = blockIdx.x;
    const int zb = r / TT, t = r % TT;
    float* row = S + (long long)zb * TT * TT + (long long)t * TT;
    const int valid = t + 1;
    const int tid = threadIdx.x;

    float mx = -1e30f;
    for (int s = tid; s < valid; s += 256) mx = fmaxf(mx, row[s]);
    red[tid] = mx; __syncthreads();
    for (int o = 128; o > 0; o >>= 1) {
        if (tid < o) red[tid] = fmaxf(red[tid], red[tid + o]);
        __syncthreads();
    }
    mx = red[0]; __syncthreads();

    float sum = 0.f;
    for (int s = tid; s < valid; s += 256) {
        float e = expf(row[s] - mx);
        row[s] = e;
        sum += e;
    }
    red[tid] = sum; __syncthreads();
    for (int o = 128; o > 0; o >>= 1) {
        if (tid < o) red[tid] += red[tid + o];
        __syncthreads();
    }
    const float inv = 1.f / red[0];

    for (int s = tid; s < valid; s += 256) row[s] = tf32r(row[s] * inv);
    const int zend = ((valid + 127) / 128) * 128;
    for (int s = valid + tid; s < zend; s += 256) row[s] = 0.f;
}

// ---------------------------------------------------------------------------
// Chamber 0 combine (In == h): v = softplus(sp0)*sigmoid(h.gw0+gb0)*(O-h)
// delta = round(v); seq = v; inb = round(h + v)   [feeds sequential iter 1]
// ---------------------------------------------------------------------------
__global__ void __launch_bounds__(256)
combine_c0_kernel(const float* __restrict__ In, const float* __restrict__ O,
                  const float* __restrict__ gw, const float* __restrict__ gb,
                  const float* __restrict__ sp,
                  float* __restrict__ delta, float* __restrict__ seq,
                  float* __restrict__ inb)
{
    __shared__ float red[256];
    const int r = blockIdx.x;
    const long long base = (long long)r * DD;
    const int tid = threadIdx.x;

    float dot = 0.f;
    for (int d = tid; d < DD; d += 256) dot += In[base + d] * gw[d];
    red[tid] = dot; __syncthreads();
    for (int o = 128; o > 0; o >>= 1) {
        if (tid < o) red[tid] += red[tid + o];
        __syncthreads();
    }
    const float gate = 1.f / (1.f + expf(-(red[0] + gb[0])));
    const float s = sp[0];
    float coef = (s > 20.f) ? s : log1pf(expf(s));
    coef *= gate;

    for (int d = tid; d < DD; d += 256) {
        const float hv = In[base + d];
        const float v = coef * (O[base + d] - hv);
        delta[base + d] = tf32r(v);
        seq[base + d] = v;
        inb[base + d] = tf32r(hv + v);
    }
}

// ---------------------------------------------------------------------------
// Parallel combine for chambers 1..6 (blockIdx.y = ch-1)
// ---------------------------------------------------------------------------
__global__ void __launch_bounds__(256)
combine_par6_kernel(const float* __restrict__ hIn, const float* __restrict__ o6,
                    const float* __restrict__ gw, const float* __restrict__ gb,
                    const float* __restrict__ sp, float* __restrict__ delta6)
{
    __shared__ float red[256];
    const int i  = blockIdx.y;
    const int r  = blockIdx.x;
    const long long base  = (long long)r * DD;
    const long long cbase = (long long)i * BT * DD + base;
    const int tid = threadIdx.x;
    const float* gwi = gw + (size_t)(i + 1) * DD;

    float dot = 0.f;
    for (int d = tid; d < DD; d += 256) dot += hIn[base + d] * gwi[d];
    red[tid] = dot; __syncthreads();
    for (int o = 128; o > 0; o >>= 1) {
        if (tid < o) red[tid] += red[tid + o];
        __syncthreads();
    }
    const float gate = 1.f / (1.f + expf(-(red[0] + gb[i + 1])));
    const float s = sp[i + 1];
    float coef = (s > 20.f) ? s : log1pf(expf(s));
    coef *= gate;

    for (int d = tid; d < DD; d += 256)
        delta6[cbase + d] = tf32r(coef * (o6[cbase + d] - hIn[base + d]));
}

// ---------------------------------------------------------------------------
// Sequential combine: seq += v; inb = round(h + seq_new)  (inb may be null)
// ---------------------------------------------------------------------------
__global__ void __launch_bounds__(256)
combine_seq_kernel(const float* __restrict__ In, const float* __restrict__ O,
                   const float* __restrict__ h,
                   const float* __restrict__ gw, const float* __restrict__ gb,
                   const float* __restrict__ sp,
                   float* __restrict__ seq, float* __restrict__ inb)
{
    __shared__ float red[256];
    const int r = blockIdx.x;
    const long long base = (long long)r * DD;
    const int tid = threadIdx.x;

    float dot = 0.f;
    for (int d = tid; d < DD; d += 256) dot += In[base + d] * gw[d];
    red[tid] = dot; __syncthreads();
    for (int o = 128; o > 0; o >>= 1) {
        if (tid < o) red[tid] += red[tid + o];
        __syncthreads();
    }
    const float gate = 1.f / (1.f + expf(-(red[0] + gb[0])));
    const float s = sp[0];
    float coef = (s > 20.f) ? s : log1pf(expf(s));
    coef *= gate;

    for (int d = tid; d < DD; d += 256) {
        const float sv = seq[base + d] + coef * (O[base + d] - In[base + d]);
        seq[base + d] = sv;
        if (inb) inb[base + d] = tf32r(h[base + d] + sv);
    }
}

// ---------------------------------------------------------------------------
// LayerNorm (per row), output TF32-rounded (feeds GEMMs)
// ---------------------------------------------------------------------------
__global__ void __launch_bounds__(256)
ln_kernel(const float* __restrict__ x, const float* __restrict__ g,
          const float* __restrict__ b, float* __restrict__ out)
{
    __shared__ float r1[256], r2[256];
    const int r = blockIdx.x;
    const long long base = (long long)r * DD;
    const int tid = threadIdx.x;

    float s = 0.f, s2 = 0.f;
    for (int d = tid; d < DD; d += 256) {
        float v = x[base + d];
        s += v; s2 += v * v;
    }
    r1[tid] = s; r2[tid] = s2; __syncthreads();
    for (int o = 128; o > 0; o >>= 1) {
        if (tid < o) { r1[tid] += r1[tid + o]; r2[tid] += r2[tid + o]; }
        __syncthreads();
    }
    const float m   = r1[0] / DD;
    const float var = r2[0] / DD - m * m;
    const float inv = rsqrtf(var + 1e-5f);
    for (int d = tid; d < DD; d += 256)
        out[base + d] = tf32r((x[base + d] - m) * inv * g[d] + b[d]);
}

// ---------------------------------------------------------------------------
__global__ void __launch_bounds__(256)
final_kernel(const float* __restrict__ x, const float* __restrict__ seq,
             const float* __restrict__ par, const float* __restrict__ g,
             const float* __restrict__ b, const float* __restrict__ mode_logit,
             const float* __restrict__ res_gate, float* __restrict__ out)
{
    __shared__ float r1[256], r2[256];
    const int r = blockIdx.x;
    const long long base = (long long)r * DD;
    const int tid = threadIdx.x;

    const float mg = 1.f / (1.f + expf(-mode_logit[0]));
    const float rg = res_gate[0];

    float s = 0.f, s2 = 0.f;
    for (int d = tid; d < DD; d += 256) {
        float e = (1.f - mg) * seq[base + d] + mg * par[base + d];
        s += e; s2 += e * e;
    }
    r1[tid] = s; r2[tid] = s2; __syncthreads();
    for (int o = 128; o > 0; o >>= 1) {
        if (tid < o) { r1[tid] += r1[tid + o]; r2[tid] += r2[tid + o]; }
        __syncthreads();
    }
    const float m   = r1[0] / DD;
    const float var = r2[0] / DD - m * m;
    const float inv = rsqrtf(var + 1e-5f);
    for (int d = tid; d < DD; d += 256) {
        float e  = (1.f - mg) * seq[base + d] + mg * par[base + d];
        float ln = (e - m) * inv * g[d] + b[d];
        out[base + d] = x[base + d] + rg * ln;
    }
}

// ---------------------------------------------------------------------------
extern "C" void kernel_launch(void* const* d_in, const int* in_sizes, int n_in,
                              void* d_out, int out_size)
{
    const float* x             = (const float*)d_in[0];
    const float* Wq            = (const float*)d_in[1];
    const float* Wk            = (const float*)d_in[2];
    const float* gate_w        = (const float*)d_in[3];
    const float* gate_b        = (const float*)d_in[4];
    const float* scale_p       = (const float*)d_in[5];
    const float* merge_W       = (const float*)d_in[6];
    const float* mode_logit    = (const float*)d_in[7];
    const float* residual_gate = (const float*)d_in[8];
    const float* ln_pre_g      = (const float*)d_in[9];
    const float* ln_pre_b      = (const float*)d_in[10];
    const float* ln_post_g     = (const float*)d_in[11];
    const float* ln_post_b     = (const float*)d_in[12];
    float* out = (float*)d_out;

    float *h, *inb, *seq, *par, *q, *k, *o, *dl, *S;
    float *qk2, *o2, *S2, *wqk, *mw;
    cudaGetSymbolAddress((void**)&h,   g_h);
    cudaGetSymbolAddress((void**)&inb, g_in);
    cudaGetSymbolAddress((void**)&seq, g_seq);
    cudaGetSymbolAddress((void**)&par, g_par);
    cudaGetSymbolAddress((void**)&q,   g_q);
    cudaGetSymbolAddress((void**)&k,   g_k);
    cudaGetSymbolAddress((void**)&o,   g_o);
    cudaGetSymbolAddress((void**)&dl,  g_d);
    cudaGetSymbolAddress((void**)&S,   g_S);
    cudaGetSymbolAddress((void**)&qk2, g_qk2);
    cudaGetSymbolAddress((void**)&o2,  g_o2);
    cudaGetSymbolAddress((void**)&S2,  g_S2);
    cudaGetSymbolAddress((void**)&wqk, g_wqk);
    cudaGetSymbolAddress((void**)&mw,  g_mw);

    // One-time host resources + dynamic-smem opt-in (first call precedes capture)
    static cudaStream_t s1 = nullptr;
    static cudaEvent_t evF1 = nullptr, evF2 = nullptr, evJ = nullptr;
    if (!s1) {
        cudaStreamCreateWithFlags(&s1, cudaStreamNonBlocking);
        cudaEventCreateWithFlags(&evF1, cudaEventDisableTiming);
        cudaEventCreateWithFlags(&evF2, cudaEventDisableTiming);
        cudaEventCreateWithFlags(&evJ,  cudaEventDisableTiming);
        cudaFuncSetAttribute(mma_gemm<false, false, false, false>,
                             cudaFuncAttributeMaxDynamicSharedMemorySize, GEMM_SMEM);
        cudaFuncSetAttribute(mma_gemm<true,  false, true,  false>,
                             cudaFuncAttributeMaxDynamicSharedMemorySize, GEMM_SMEM);
        cudaFuncSetAttribute(mma_gemm<false, false, false, true >,
                             cudaFuncAttributeMaxDynamicSharedMemorySize, GEMM_SMEM);
        cudaFuncSetAttribute(mma_gemm<true,  false, false, false>,
                             cudaFuncAttributeMaxDynamicSharedMemorySize, GEMM_SMEM);
    }

    const float isd = 1.f / sqrtf((float)DD);
    const long long sQK  = (long long)DD * DD;
    const long long sRow = (long long)BT * DD;
    const long long sBT  = (long long)TT * DD;
    const long long sS   = (long long)TT * TT;
    const int wn4 = NCH * DD * DD / 4;
    float* q2 = qk2;
    float* k2 = qk2 + sRow;

    // -------- weight rounding (interleaved q|k) + pre-LN --------------------
    round_inter_kernel<<<(wn4 + 255) / 256, 256>>>(Wq, wqk, 0, wn4);
    round_inter_kernel<<<(wn4 + 255) / 256, 256>>>(Wk, wqk, 1, wn4);
    ln_kernel<<<BT, 256>>>(x, ln_pre_g, ln_pre_b, h);

    // -------- fork: s1 runs parallel chambers 1..6 + merge weight round ----
    cudaEventRecord(evF1, 0);
    cudaStreamWaitEvent(s1, evF1, 0);

    round_tf32_kernel<<<(wn4 + 255) / 256, 256, 0, s1>>>(merge_W, mw, wn4);
    // Q_i = h @ Wq_i (chambers 1..6): interleaved weights, stride 2*sQK
    mma_gemm<false, false, false, false><<<dim3(6, 32, 6), 256, GEMM_SMEM, s1>>>(
        h, DD, 0, wqk + 2 * sQK, DD, 2 * sQK, 0, q + sRow, DD, sRow, BT, DD, DD, 1.f, 0, 0);
    mma_gemm<false, false, false, false><<<dim3(6, 32, 6), 256, GEMM_SMEM, s1>>>(
        h, DD, 0, wqk + 3 * sQK, DD, 2 * sQK, 0, k + sRow, DD, sRow, BT, DD, DD, 1.f, 0, 0);
    mma_gemm<true, false, true, false><<<dim3(8, 8, 24), 256, GEMM_SMEM, s1>>>(
        q + sRow, DD, sBT, k + sRow, DD, sBT, 0, S, TT, sS, TT, TT, DD, isd, 0, 0);
    softmax_causal_kernel<<<24 * TT, 256, 0, s1>>>(S);
    mma_gemm<false, false, false, true><<<dim3(6, 8, 24), 256, GEMM_SMEM, s1>>>(
        S, TT, sS, h, DD, sBT, BB, o + sRow, DD, sBT, TT, DD, TT, 1.f, 0, 0);
    combine_par6_kernel<<<dim3(BT, 6), 256, 0, s1>>>(
        h, o + sRow, gate_w, gate_b, scale_p, dl + sRow);

    // -------- chamber 0 on stream 0 (fused Q|K launch, z=2) -----------------
    mma_gemm<false, false, false, false><<<dim3(6, 32, 2), 256, GEMM_SMEM>>>(
        h, DD, 0, wqk, DD, sQK, 0, qk2, DD, sRow, BT, DD, DD, 1.f, 0, 0);
    mma_gemm<true, false, true, false><<<dim3(8, 8, BB), 256, GEMM_SMEM>>>(
        q2, DD, sBT, k2, DD, sBT, 0, S2, TT, sS, TT, TT, DD, isd, 0, 0);
    softmax_causal_kernel<<<BB * TT, 256>>>(S2);
    mma_gemm<false, false, false, true><<<dim3(6, 8, BB), 256, GEMM_SMEM>>>(
        S2, TT, sS, h, DD, sBT, 0, o2, DD, sBT, TT, DD, TT, 1.f, 0, 0);
    combine_c0_kernel<<<BT, 256>>>(h, o2, gate_w, gate_b, scale_p, dl, seq, inb);

    // delta_0 ready -> merge GEMM on s1 (single K=7*768 GEMM, A chunked)
    cudaEventRecord(evF2, 0);
    cudaStreamWaitEvent(s1, evF2, 0);
    mma_gemm<true, false, false, false><<<dim3(6, 32, 1), 256, GEMM_SMEM, s1>>>(
        dl, DD, 0, mw, NCH * DD, 0, 0, par, DD, 0,
        BT, DD, NCH * DD, 1.f, DD, sRow);
    cudaEventRecord(evJ, s1);

    // -------- sequential chambers 1..6 on stream 0 -------------------------
    for (int i = 1; i < NCH; i++) {
        // fused Q|K projection from inb (z=2)
        mma_gemm<false, false, false, false><<<dim3(6, 32, 2), 256, GEMM_SMEM>>>(
            inb, DD, 0, wqk + (size_t)i * 2 * sQK, DD, sQK, 0,
            qk2, DD, sRow, BT, DD, DD, 1.f, 0, 0);
        mma_gemm<true, false, true, false><<<dim3(8, 8, BB), 256, GEMM_SMEM>>>(
            q2, DD, sBT, k2, DD, sBT, 0, S2, TT, sS, TT, TT, DD, isd, 0, 0);
        softmax_causal_kernel<<<BB * TT, 256>>>(S2);
        mma_gemm<false, false, false, true><<<dim3(6, 8, BB), 256, GEMM_SMEM>>>(
            S2, TT, sS, inb, DD, sBT, 0, o2, DD, sBT, TT, DD, TT, 1.f, 0, 0);
        combine_seq_kernel<<<BT, 256>>>(inb, o2, h, gate_w + (size_t)i * DD,
                                        gate_b + i, scale_p + i, seq,
                                        (i + 1 < NCH) ? inb : nullptr);
    }

    // -------- join + finalize ----------------------------------------------
    cudaStreamWaitEvent(0, evJ, 0);
    final_kernel<<<BT, 256>>>(x, seq, par, ln_post_g, ln_post_b,
                              mode_logit, residual_gate, out);
}

// round 13
// speedup vs baseline: 1.5992x; 1.5992x over previous
#include <cuda_runtime.h>
#include <cuda_bf16.h>
#include <stdint.h>
#include <math.h>

// Problem constants
#define BB  4
#define TT  1024
#define DD  768
#define NCH 7
#define BT  (BB*TT)   // 4096 rows

typedef __nv_bfloat16 bf16;

// ---------------------------------------------------------------------------
// Scratch (device globals; no allocation in kernel_launch)
// ---------------------------------------------------------------------------
__device__ float g_h   [(size_t)BT*DD];            // fp32 LN output (elementwise)
__device__ float g_seq [(size_t)BT*DD];
__device__ float g_par [(size_t)BT*DD];
__device__ bf16  g_hb  [(size_t)BT*DD];            // bf16 GEMM operand copy of h
__device__ bf16  g_in  [(size_t)BT*DD];            // bf16 (h+seq) GEMM operand
// parallel branch (chambers 1..6 in slots 1..6)
__device__ bf16  g_q   [(size_t)NCH*BT*DD];
__device__ bf16  g_k   [(size_t)NCH*BT*DD];
__device__ bf16  g_o   [(size_t)NCH*BT*DD];
__device__ bf16  g_d   [(size_t)NCH*BT*DD];
__device__ bf16  g_S   [(size_t)NCH*BB*TT*TT];     // 58.7 MB bf16 scores/probs
// sequential-branch private buffers
__device__ bf16  g_qk2 [(size_t)2*BT*DD];          // fused Q|K output
__device__ bf16  g_o2  [(size_t)BT*DD];
__device__ bf16  g_S2  [(size_t)BB*TT*TT];
// bf16 weights: interleaved [chamber][q|k][D][D], plus merge
__device__ bf16  g_wqk [(size_t)NCH*2*DD*DD];
__device__ bf16  g_mw  [(size_t)DD*NCH*DD];

// ---------------------------------------------------------------------------
// MMA helpers
// ---------------------------------------------------------------------------
__device__ __forceinline__ void mma_bf16(float c[4],
    uint32_t a0, uint32_t a1, uint32_t a2, uint32_t a3,
    uint32_t b0, uint32_t b1)
{
    asm volatile(
        "mma.sync.aligned.m16n8k16.row.col.f32.bf16.bf16.f32 "
        "{%0,%1,%2,%3}, {%4,%5,%6,%7}, {%8,%9}, {%0,%1,%2,%3};"
        : "+f"(c[0]), "+f"(c[1]), "+f"(c[2]), "+f"(c[3])
        : "r"(a0), "r"(a1), "r"(a2), "r"(a3), "r"(b0), "r"(b1));
}
#define CPA16(saddr, gptr) \
    asm volatile("cp.async.cg.shared.global [%0], [%1], 16;" :: "r"(saddr), "l"(gptr))
#define CPA_COMMIT() asm volatile("cp.async.commit_group;")
#define CPA_WAIT2()  asm volatile("cp.async.wait_group 2;")

// ---------------------------------------------------------------------------
// BF16 MMA GEMM, 4-stage cp.async pipeline, dynamic smem.
// C = alpha * A @ op(B); all inputs bf16, accumulate fp32,
// output bf16 (OUTBF) or fp32.
//   A: M x K row-major (lda elems). kchunk>0: K-concat of chunks (merge GEMM).
//   B: TRANSB ? N x K row-major : K x N row-major. bmod>0 -> B uses z%bmod.
//   CSKIP: skip C tiles fully above diagonal. CKLIM: cap K at tile diagonal.
// Tiles 128x128x32, 8 warps, 64x32 warp tile, m16n8k16 fragments.
// ---------------------------------------------------------------------------
#define ASTRIDE 40            // bf16 elems per smem row (80B, conflict-free)
#define BSTRIDE 136           // k-major B rows (272B)
#define AS_SZ  (128*ASTRIDE)  // 5120 bf16
#define STG_SZ (2*AS_SZ)      // 10240 bf16 = 20 KB per stage
#define NSTG   4
#define GEMM_SMEM (NSTG*STG_SZ*(int)sizeof(bf16))   // 81920 B

template<bool TRANSB, bool CSKIP, bool CKLIM, bool OUTBF>
__global__ void __launch_bounds__(256, 2)
mma_gemm(const bf16* __restrict__ A, int lda, long long sA,
         const bf16* __restrict__ Bp, int ldb, long long sB, int bmod,
         void* __restrict__ Cv, int ldc, long long sC,
         int M, int N, int K, float alpha,
         int kchunk, long long schunk)
{
    extern __shared__ bf16 smdyn[];

    const int m0 = blockIdx.y * 128;
    const int n0 = blockIdx.x * 128;
    if (CSKIP && n0 > m0 + 127) return;

    const int z = blockIdx.z;
    A  += (long long)z * sA;
    Bp += (long long)(bmod ? (z % bmod) : z) * sB;

    int kend = K;
    if (CKLIM) { int ke = m0 + 128; kend = (ke < K) ? ke : K; }
    const int niter = kend >> 5;   // BK = 32; niter >= 4 for all launches

    const int tid  = threadIdx.x;
    const int wid  = tid >> 5;
    const int lane = tid & 31;
    const int gid  = lane >> 2;
    const int tig  = lane & 3;
    const int wm   = (wid & 1) * 64;
    const int wn   = (wid >> 1) * 32;

    float acc[4][4][4];
    #pragma unroll
    for (int i = 0; i < 4; i++)
        #pragma unroll
        for (int j = 0; j < 4; j++)
            #pragma unroll
            for (int r = 0; r < 4; r++) acc[i][j][r] = 0.f;

    auto loadA = [&](int stg, int k0) {
        const bf16* Ab;
        if (kchunk) { int c = k0 / kchunk; Ab = A + (long long)c * schunk + (k0 - c * kchunk); }
        else        Ab = A + k0;
        bf16* as = smdyn + stg * STG_SZ;
        #pragma unroll
        for (int i = 0; i < 2; i++) {
            int idx = tid + i * 256;
            int r = idx >> 2, c8 = (idx & 3) << 3;            // 4 x 16B chunks / row
            uint32_t sa = (uint32_t)__cvta_generic_to_shared(&as[r * ASTRIDE + c8]);
            CPA16(sa, Ab + (long long)(m0 + r) * lda + c8);
        }
    };
    auto loadB = [&](int stg, int k0) {
        bf16* bs = smdyn + stg * STG_SZ + AS_SZ;
        if (TRANSB) {
            #pragma unroll
            for (int i = 0; i < 2; i++) {
                int idx = tid + i * 256;
                int r = idx >> 2, c8 = (idx & 3) << 3;
                uint32_t sa = (uint32_t)__cvta_generic_to_shared(&bs[r * ASTRIDE + c8]);
                CPA16(sa, Bp + (long long)(n0 + r) * ldb + k0 + c8);
            }
        } else {
            #pragma unroll
            for (int i = 0; i < 2; i++) {
                int idx = tid + i * 256;
                int r = idx >> 4, c8 = (idx & 15) << 3;        // 16 x 16B chunks / row
                uint32_t sa = (uint32_t)__cvta_generic_to_shared(&bs[r * BSTRIDE + c8]);
                CPA16(sa, Bp + (long long)(k0 + r) * ldb + n0 + c8);
            }
        }
    };

    // prologue: stages 0,1,2
    loadA(0, 0);       loadB(0, 0);       CPA_COMMIT();
    loadA(1, 1 << 5);  loadB(1, 1 << 5);  CPA_COMMIT();
    loadA(2, 2 << 5);  loadB(2, 2 << 5);  CPA_COMMIT();

    for (int it = 0; it < niter; ++it) {
        CPA_WAIT2();
        __syncthreads();
        const int ld = it + 3;
        if (ld < niter) { loadA(ld & 3, ld << 5); loadB(ld & 3, ld << 5); }
        CPA_COMMIT();

        const bf16* as = smdyn + (it & 3) * STG_SZ;
        const bf16* bs = as + AS_SZ;

        #pragma unroll
        for (int kk = 0; kk < 32; kk += 16) {
            uint32_t a[4][4];
            #pragma unroll
            for (int mi = 0; mi < 4; mi++) {
                int mb = wm + mi * 16 + gid;
                a[mi][0] = *reinterpret_cast<const uint32_t*>(&as[ mb      * ASTRIDE + kk + 2 * tig    ]);
                a[mi][1] = *reinterpret_cast<const uint32_t*>(&as[(mb + 8) * ASTRIDE + kk + 2 * tig    ]);
                a[mi][2] = *reinterpret_cast<const uint32_t*>(&as[ mb      * ASTRIDE + kk + 2 * tig + 8]);
                a[mi][3] = *reinterpret_cast<const uint32_t*>(&as[(mb + 8) * ASTRIDE + kk + 2 * tig + 8]);
            }
            uint32_t b[4][2];
            #pragma unroll
            for (int ni = 0; ni < 4; ni++) {
                int nb = wn + ni * 8 + gid;
                if (TRANSB) {
                    b[ni][0] = *reinterpret_cast<const uint32_t*>(&bs[nb * ASTRIDE + kk + 2 * tig    ]);
                    b[ni][1] = *reinterpret_cast<const uint32_t*>(&bs[nb * ASTRIDE + kk + 2 * tig + 8]);
                } else {
                    const unsigned short* bsu = reinterpret_cast<const unsigned short*>(bs);
                    uint32_t l0 = bsu[(kk + 2 * tig    ) * BSTRIDE + nb];
                    uint32_t h0 = bsu[(kk + 2 * tig + 1) * BSTRIDE + nb];
                    uint32_t l1 = bsu[(kk + 2 * tig + 8) * BSTRIDE + nb];
                    uint32_t h1 = bsu[(kk + 2 * tig + 9) * BSTRIDE + nb];
                    b[ni][0] = l0 | (h0 << 16);
                    b[ni][1] = l1 | (h1 << 16);
                }
            }
            #pragma unroll
            for (int mi = 0; mi < 4; mi++)
                #pragma unroll
                for (int ni = 0; ni < 4; ni++)
                    mma_bf16(acc[mi][ni], a[mi][0], a[mi][1], a[mi][2], a[mi][3],
                             b[ni][0], b[ni][1]);
        }
    }

    // epilogue
    #pragma unroll
    for (int mi = 0; mi < 4; mi++) {
        #pragma unroll
        for (int ni = 0; ni < 4; ni++) {
            const int rr = m0 + wm + mi * 16 + gid;
            const int cc = n0 + wn + ni * 8 + tig * 2;
            #pragma unroll
            for (int hh = 0; hh < 2; hh++) {
                long long idx = ((long long)z * sC) + (long long)(rr + hh * 8) * ldc + cc;
                float vx = alpha * acc[mi][ni][hh * 2 + 0];
                float vy = alpha * acc[mi][ni][hh * 2 + 1];
                if (OUTBF) {
                    __nv_bfloat162 v2;
                    v2.x = __float2bfloat16(vx);
                    v2.y = __float2bfloat16(vy);
                    *reinterpret_cast<__nv_bfloat162*>(&((bf16*)Cv)[idx]) = v2;
                } else {
                    float2 v; v.x = vx; v.y = vy;
                    *reinterpret_cast<float2*>(&((float*)Cv)[idx]) = v;
                }
            }
        }
    }
}

// ---------------------------------------------------------------------------
// fp32 -> bf16 conversion kernels (weights)
// ---------------------------------------------------------------------------
__device__ __forceinline__ void store_bf4(bf16* dst, float4 v) {
    __nv_bfloat162 lo, hi;
    lo.x = __float2bfloat16(v.x); lo.y = __float2bfloat16(v.y);
    hi.x = __float2bfloat16(v.z); hi.y = __float2bfloat16(v.w);
    *reinterpret_cast<__nv_bfloat162*>(dst)     = lo;
    *reinterpret_cast<__nv_bfloat162*>(dst + 2) = hi;
}

__global__ void cvt_bf16_kernel(const float* __restrict__ in,
                                bf16* __restrict__ out, int n4)
{
    int i = blockIdx.x * 256 + threadIdx.x;
    if (i < n4) store_bf4(out + (size_t)i * 4, reinterpret_cast<const float4*>(in)[i]);
}

// Convert + interleave into wqk[(2*chamber+which)*D*D + rem]
__global__ void cvt_inter_kernel(const float* __restrict__ in,
                                 bf16* __restrict__ out, int which, int n4)
{
    const int q4 = DD * DD / 4;
    int i = blockIdx.x * 256 + threadIdx.x;
    if (i < n4) {
        int c = i / q4, rem = i - c * q4;
        store_bf4(out + ((size_t)(2 * c + which) * q4 + rem) * 4,
                  reinterpret_cast<const float4*>(in)[i]);
    }
}

// ---------------------------------------------------------------------------
// Causal softmax over bf16 rows of [nz][T][T]: one read + one write.
// Each thread holds 4 strided elements in registers. Zeros for s > t.
// ---------------------------------------------------------------------------
__global__ void __launch_bounds__(256)
softmax_causal_kernel(bf16* __restrict__ S)
{
    __shared__ float red[256];
    const int r = blockIdx.x;
    const int zb = r / TT, t = r % TT;
    bf16* row = S + (long long)zb * TT * TT + (long long)t * TT;
    const int valid = t + 1;
    const int tid = threadIdx.x;

    float v[4];
    #pragma unroll
    for (int j = 0; j < 4; j++) {
        int s = tid + j * 256;
        v[j] = (s < valid) ? __bfloat162float(row[s]) : -1e30f;
    }
    float mx = fmaxf(fmaxf(v[0], v[1]), fmaxf(v[2], v[3]));
    red[tid] = mx; __syncthreads();
    for (int o = 128; o > 0; o >>= 1) {
        if (tid < o) red[tid] = fmaxf(red[tid], red[tid + o]);
        __syncthreads();
    }
    mx = red[0]; __syncthreads();

    float sum = 0.f;
    #pragma unroll
    for (int j = 0; j < 4; j++) {
        int s = tid + j * 256;
        v[j] = (s < valid) ? expf(v[j] - mx) : 0.f;
        sum += v[j];
    }
    red[tid] = sum; __syncthreads();
    for (int o = 128; o > 0; o >>= 1) {
        if (tid < o) red[tid] += red[tid + o];
        __syncthreads();
    }
    const float inv = 1.f / red[0];

    #pragma unroll
    for (int j = 0; j < 4; j++) {
        int s = tid + j * 256;
        row[s] = __float2bfloat16(v[j] * inv);
    }
}

// ---------------------------------------------------------------------------
// Chamber 0 combine (In == h fp32): v = softplus(sp0)*sigmoid(h.gw0+gb0)*(O-h)
// delta = bf16(v); seq = v; inb = bf16(h + v)
// ---------------------------------------------------------------------------
__global__ void __launch_bounds__(256)
combine_c0_kernel(const float* __restrict__ h, const bf16* __restrict__ O,
                  const float* __restrict__ gw, const float* __restrict__ gb,
                  const float* __restrict__ sp,
                  bf16* __restrict__ delta, float* __restrict__ seq,
                  bf16* __restrict__ inb)
{
    __shared__ float red[256];
    const int r = blockIdx.x;
    const long long base = (long long)r * DD;
    const int tid = threadIdx.x;

    float dot = 0.f;
    for (int d = tid; d < DD; d += 256) dot += h[base + d] * gw[d];
    red[tid] = dot; __syncthreads();
    for (int o = 128; o > 0; o >>= 1) {
        if (tid < o) red[tid] += red[tid + o];
        __syncthreads();
    }
    const float gate = 1.f / (1.f + expf(-(red[0] + gb[0])));
    const float s = sp[0];
    float coef = (s > 20.f) ? s : log1pf(expf(s));
    coef *= gate;

    for (int d = tid; d < DD; d += 256) {
        const float hv = h[base + d];
        const float v = coef * (__bfloat162float(O[base + d]) - hv);
        delta[base + d] = __float2bfloat16(v);
        seq[base + d] = v;
        inb[base + d] = __float2bfloat16(hv + v);
    }
}

// ---------------------------------------------------------------------------
// Parallel combine for chambers 1..6 (blockIdx.y = ch-1)
// ---------------------------------------------------------------------------
__global__ void __launch_bounds__(256)
combine_par6_kernel(const float* __restrict__ h, const bf16* __restrict__ o6,
                    const float* __restrict__ gw, const float* __restrict__ gb,
                    const float* __restrict__ sp, bf16* __restrict__ delta6)
{
    __shared__ float red[256];
    const int i  = blockIdx.y;
    const int r  = blockIdx.x;
    const long long base  = (long long)r * DD;
    const long long cbase = (long long)i * BT * DD + base;
    const int tid = threadIdx.x;
    const float* gwi = gw + (size_t)(i + 1) * DD;

    float dot = 0.f;
    for (int d = tid; d < DD; d += 256) dot += h[base + d] * gwi[d];
    red[tid] = dot; __syncthreads();
    for (int o = 128; o > 0; o >>= 1) {
        if (tid < o) red[tid] += red[tid + o];
        __syncthreads();
    }
    const float gate = 1.f / (1.f + expf(-(red[0] + gb[i + 1])));
    const float s = sp[i + 1];
    float coef = (s > 20.f) ? s : log1pf(expf(s));
    coef *= gate;

    for (int d = tid; d < DD; d += 256)
        delta6[cbase + d] = __float2bfloat16(
            coef * (__bfloat162float(o6[cbase + d]) - h[base + d]));
}

// ---------------------------------------------------------------------------
// Sequential combine: In = h + seq_old (fp32); seq += coef*(O - In);
// inb = bf16(h + seq_new)  (inb may be null on the last iteration)
// ---------------------------------------------------------------------------
__global__ void __launch_bounds__(256)
combine_seq_kernel(const float* __restrict__ h, const bf16* __restrict__ O,
                   const float* __restrict__ gw, const float* __restrict__ gb,
                   const float* __restrict__ sp,
                   float* __restrict__ seq, bf16* __restrict__ inb)
{
    __shared__ float red[256];
    const int r = blockIdx.x;
    const long long base = (long long)r * DD;
    const int tid = threadIdx.x;

    float dot = 0.f;
    for (int d = tid; d < DD; d += 256)
        dot += (h[base + d] + seq[base + d]) * gw[d];
    red[tid] = dot; __syncthreads();
    for (int o = 128; o > 0; o >>= 1) {
        if (tid < o) red[tid] += red[tid + o];
        __syncthreads();
    }
    const float gate = 1.f / (1.f + expf(-(red[0] + gb[0])));
    const float s = sp[0];
    float coef = (s > 20.f) ? s : log1pf(expf(s));
    coef *= gate;

    for (int d = tid; d < DD; d += 256) {
        const float hv = h[base + d];
        const float In = hv + seq[base + d];
        const float sv = seq[base + d] + coef * (__bfloat162float(O[base + d]) - In);
        seq[base + d] = sv;
        if (inb) inb[base + d] = __float2bfloat16(hv + sv);
    }
}

// ---------------------------------------------------------------------------
// LayerNorm: writes fp32 h (exact) + bf16 copy for GEMMs
// ---------------------------------------------------------------------------
__global__ void __launch_bounds__(256)
ln_kernel(const float* __restrict__ x, const float* __restrict__ g,
          const float* __restrict__ b, float* __restrict__ out,
          bf16* __restrict__ outb)
{
    __shared__ float r1[256], r2[256];
    const int r = blockIdx.x;
    const long long base = (long long)r * DD;
    const int tid = threadIdx.x;

    float s = 0.f, s2 = 0.f;
    for (int d = tid; d < DD; d += 256) {
        float v = x[base + d];
        s += v; s2 += v * v;
    }
    r1[tid] = s; r2[tid] = s2; __syncthreads();
    for (int o = 128; o > 0; o >>= 1) {
        if (tid < o) { r1[tid] += r1[tid + o]; r2[tid] += r2[tid + o]; }
        __syncthreads();
    }
    const float m   = r1[0] / DD;
    const float var = r2[0] / DD - m * m;
    const float inv = rsqrtf(var + 1e-5f);
    for (int d = tid; d < DD; d += 256) {
        float v = (x[base + d] - m) * inv * g[d] + b[d];
        out[base + d]  = v;
        outb[base + d] = __float2bfloat16(v);
    }
}

// ---------------------------------------------------------------------------
__global__ void __launch_bounds__(256)
final_kernel(const float* __restrict__ x, const float* __restrict__ seq,
             const float* __restrict__ par, const float* __restrict__ g,
             const float* __restrict__ b, const float* __restrict__ mode_logit,
             const float* __restrict__ res_gate, float* __restrict__ out)
{
    __shared__ float r1[256], r2[256];
    const int r = blockIdx.x;
    const long long base = (long long)r * DD;
    const int tid = threadIdx.x;

    const float mg = 1.f / (1.f + expf(-mode_logit[0]));
    const float rg = res_gate[0];

    float s = 0.f, s2 = 0.f;
    for (int d = tid; d < DD; d += 256) {
        float e = (1.f - mg) * seq[base + d] + mg * par[base + d];
        s += e; s2 += e * e;
    }
    r1[tid] = s; r2[tid] = s2; __syncthreads();
    for (int o = 128; o > 0; o >>= 1) {
        if (tid < o) { r1[tid] += r1[tid + o]; r2[tid] += r2[tid + o]; }
        __syncthreads();
    }
    const float m   = r1[0] / DD;
    const float var = r2[0] / DD - m * m;
    const float inv = rsqrtf(var + 1e-5f);
    for (int d = tid; d < DD; d += 256) {
        float e  = (1.f - mg) * seq[base + d] + mg * par[base + d];
        float ln = (e - m) * inv * g[d] + b[d];
        out[base + d] = x[base + d] + rg * ln;
    }
}

// ---------------------------------------------------------------------------
extern "C" void kernel_launch(void* const* d_in, const int* in_sizes, int n_in,
                              void* d_out, int out_size)
{
    const float* x             = (const float*)d_in[0];
    const float* Wq            = (const float*)d_in[1];
    const float* Wk            = (const float*)d_in[2];
    const float* gate_w        = (const float*)d_in[3];
    const float* gate_b        = (const float*)d_in[4];
    const float* scale_p       = (const float*)d_in[5];
    const float* merge_W       = (const float*)d_in[6];
    const float* mode_logit    = (const float*)d_in[7];
    const float* residual_gate = (const float*)d_in[8];
    const float* ln_pre_g      = (const float*)d_in[9];
    const float* ln_pre_b      = (const float*)d_in[10];
    const float* ln_post_g     = (const float*)d_in[11];
    const float* ln_post_b     = (const float*)d_in[12];
    float* out = (float*)d_out;

    float *h, *seq, *par;
    bf16 *hb, *inb, *q, *k, *o, *dl, *S, *qk2, *o2, *S2, *wqk, *mw;
    cudaGetSymbolAddress((void**)&h,   g_h);
    cudaGetSymbolAddress((void**)&seq, g_seq);
    cudaGetSymbolAddress((void**)&par, g_par);
    cudaGetSymbolAddress((void**)&hb,  g_hb);
    cudaGetSymbolAddress((void**)&inb, g_in);
    cudaGetSymbolAddress((void**)&q,   g_q);
    cudaGetSymbolAddress((void**)&k,   g_k);
    cudaGetSymbolAddress((void**)&o,   g_o);
    cudaGetSymbolAddress((void**)&dl,  g_d);
    cudaGetSymbolAddress((void**)&S,   g_S);
    cudaGetSymbolAddress((void**)&qk2, g_qk2);
    cudaGetSymbolAddress((void**)&o2,  g_o2);
    cudaGetSymbolAddress((void**)&S2,  g_S2);
    cudaGetSymbolAddress((void**)&wqk, g_wqk);
    cudaGetSymbolAddress((void**)&mw,  g_mw);

    // One-time host resources + dynamic-smem opt-in
    static cudaStream_t s1 = nullptr;
    static cudaEvent_t evF1 = nullptr, evF2 = nullptr, evJ = nullptr;
    if (!s1) {
        cudaStreamCreateWithFlags(&s1, cudaStreamNonBlocking);
        cudaEventCreateWithFlags(&evF1, cudaEventDisableTiming);
        cudaEventCreateWithFlags(&evF2, cudaEventDisableTiming);
        cudaEventCreateWithFlags(&evJ,  cudaEventDisableTiming);
        cudaFuncSetAttribute(mma_gemm<false, false, false, true >,   // projections
                             cudaFuncAttributeMaxDynamicSharedMemorySize, GEMM_SMEM);
        cudaFuncSetAttribute(mma_gemm<true,  true,  false, true >,   // QK^T causal
                             cudaFuncAttributeMaxDynamicSharedMemorySize, GEMM_SMEM);
        cudaFuncSetAttribute(mma_gemm<false, false, true,  true >,   // P@V
                             cudaFuncAttributeMaxDynamicSharedMemorySize, GEMM_SMEM);
        cudaFuncSetAttribute(mma_gemm<true,  false, false, false>,   // merge (fp32 out)
                             cudaFuncAttributeMaxDynamicSharedMemorySize, GEMM_SMEM);
    }

    const float isd = 1.f / sqrtf((float)DD);
    const long long sQK  = (long long)DD * DD;
    const long long sRow = (long long)BT * DD;
    const long long sBT  = (long long)TT * DD;
    const long long sS   = (long long)TT * TT;
    const int wn4 = NCH * DD * DD / 4;
    bf16* q2 = qk2;
    bf16* k2 = qk2 + sRow;

    // -------- weight conversion (interleaved q|k) + pre-LN ------------------
    cvt_inter_kernel<<<(wn4 + 255) / 256, 256>>>(Wq, wqk, 0, wn4);
    cvt_inter_kernel<<<(wn4 + 255) / 256, 256>>>(Wk, wqk, 1, wn4);
    ln_kernel<<<BT, 256>>>(x, ln_pre_g, ln_pre_b, h, hb);

    // -------- fork: s1 runs parallel chambers 1..6 + merge weight cvt ------
    cudaEventRecord(evF1, 0);
    cudaStreamWaitEvent(s1, evF1, 0);

    cvt_bf16_kernel<<<(wn4 + 255) / 256, 256, 0, s1>>>(merge_W, mw, wn4);
    mma_gemm<false, false, false, true><<<dim3(6, 32, 6), 256, GEMM_SMEM, s1>>>(
        hb, DD, 0, wqk + 2 * sQK, DD, 2 * sQK, 0, q + sRow, DD, sRow, BT, DD, DD, 1.f, 0, 0);
    mma_gemm<false, false, false, true><<<dim3(6, 32, 6), 256, GEMM_SMEM, s1>>>(
        hb, DD, 0, wqk + 3 * sQK, DD, 2 * sQK, 0, k + sRow, DD, sRow, BT, DD, DD, 1.f, 0, 0);
    mma_gemm<true, true, false, true><<<dim3(8, 8, 24), 256, GEMM_SMEM, s1>>>(
        q + sRow, DD, sBT, k + sRow, DD, sBT, 0, S, TT, sS, TT, TT, DD, isd, 0, 0);
    softmax_causal_kernel<<<24 * TT, 256, 0, s1>>>(S);
    mma_gemm<false, false, true, true><<<dim3(6, 8, 24), 256, GEMM_SMEM, s1>>>(
        S, TT, sS, hb, DD, sBT, BB, o + sRow, DD, sBT, TT, DD, TT, 1.f, 0, 0);
    combine_par6_kernel<<<dim3(BT, 6), 256, 0, s1>>>(
        h, o + sRow, gate_w, gate_b, scale_p, dl + sRow);

    // -------- chamber 0 on stream 0 (fused Q|K launch, z=2) -----------------
    mma_gemm<false, false, false, true><<<dim3(6, 32, 2), 256, GEMM_SMEM>>>(
        hb, DD, 0, wqk, DD, sQK, 0, qk2, DD, sRow, BT, DD, DD, 1.f, 0, 0);
    mma_gemm<true, true, false, true><<<dim3(8, 8, BB), 256, GEMM_SMEM>>>(
        q2, DD, sBT, k2, DD, sBT, 0, S2, TT, sS, TT, TT, DD, isd, 0, 0);
    softmax_causal_kernel<<<BB * TT, 256>>>(S2);
    mma_gemm<false, false, true, true><<<dim3(6, 8, BB), 256, GEMM_SMEM>>>(
        S2, TT, sS, hb, DD, sBT, 0, o2, DD, sBT, TT, DD, TT, 1.f, 0, 0);
    combine_c0_kernel<<<BT, 256>>>(h, o2, gate_w, gate_b, scale_p, dl, seq, inb);

    // delta_0 ready -> merge GEMM on s1 (single K=7*768 GEMM, A chunked)
    cudaEventRecord(evF2, 0);
    cudaStreamWaitEvent(s1, evF2, 0);
    mma_gemm<true, false, false, false><<<dim3(6, 32, 1), 256, GEMM_SMEM, s1>>>(
        dl, DD, 0, mw, NCH * DD, 0, 0, par, DD, 0,
        BT, DD, NCH * DD, 1.f, DD, sRow);
    cudaEventRecord(evJ, s1);

    // -------- sequential chambers 1..6 on stream 0 -------------------------
    for (int i = 1; i < NCH; i++) {
        mma_gemm<false, false, false, true><<<dim3(6, 32, 2), 256, GEMM_SMEM>>>(
            inb, DD, 0, wqk + (size_t)i * 2 * sQK, DD, sQK, 0,
            qk2, DD, sRow, BT, DD, DD, 1.f, 0, 0);
        mma_gemm<true, true, false, true><<<dim3(8, 8, BB), 256, GEMM_SMEM>>>(
            q2, DD, sBT, k2, DD, sBT, 0, S2, TT, sS, TT, TT, DD, isd, 0, 0);
        softmax_causal_kernel<<<BB * TT, 256>>>(S2);
        mma_gemm<false, false, true, true><<<dim3(6, 8, BB), 256, GEMM_SMEM>>>(
            S2, TT, sS, inb, DD, sBT, 0, o2, DD, sBT, TT, DD, TT, 1.f, 0, 0);
        combine_seq_kernel<<<BT, 256>>>(h, o2, gate_w + (size_t)i * DD,
                                        gate_b + i, scale_p + i, seq,
                                        (i + 1 < NCH) ? inb : nullptr);
    }

    // -------- join + finalize ----------------------------------------------
    cudaStreamWaitEvent(0, evJ, 0);
    final_kernel<<<BT, 256>>>(x, seq, par, ln_post_g, ln_post_b,
                              mode_logit, residual_gate, out);
}

// round 14
// speedup vs baseline: 1.9243x; 1.2033x over previous
#include <cuda_runtime.h>
#include <cuda_bf16.h>
#include <stdint.h>
#include <math.h>

// Problem constants
#define BB  4
#define TT  1024
#define DD  768
#define NCH 7
#define BT  (BB*TT)   // 4096 rows

typedef __nv_bfloat16 bf16;

// ---------------------------------------------------------------------------
// Scratch (device globals; no allocation in kernel_launch)
// ---------------------------------------------------------------------------
__device__ float g_h   [(size_t)BT*DD];            // fp32 LN output
__device__ float g_seq [(size_t)BT*DD];
__device__ float g_par [(size_t)BT*DD];
__device__ bf16  g_hb  [(size_t)BT*DD];            // bf16 GEMM operand copy of h
__device__ bf16  g_in  [(size_t)BT*DD];            // bf16 (h+seq) GEMM operand
// parallel branch (chambers 1..6 in slots 1..6)
__device__ bf16  g_q   [(size_t)NCH*BT*DD];
__device__ bf16  g_k   [(size_t)NCH*BT*DD];
__device__ bf16  g_o   [(size_t)NCH*BT*DD];
__device__ bf16  g_d   [(size_t)NCH*BT*DD];
__device__ bf16  g_S   [(size_t)NCH*BB*TT*TT];
// sequential-branch private buffers
__device__ bf16  g_qk2 [(size_t)2*BT*DD];
__device__ bf16  g_o2  [(size_t)BT*DD];
__device__ bf16  g_S2  [(size_t)BB*TT*TT];
// bf16 weights: interleaved [chamber][q|k][D][D], plus merge
__device__ bf16  g_wqk [(size_t)NCH*2*DD*DD];
__device__ bf16  g_mw  [(size_t)DD*NCH*DD];

// ---------------------------------------------------------------------------
// MMA / LDSM helpers
// ---------------------------------------------------------------------------
__device__ __forceinline__ void mma_bf16(float c[4],
    uint32_t a0, uint32_t a1, uint32_t a2, uint32_t a3,
    uint32_t b0, uint32_t b1)
{
    asm volatile(
        "mma.sync.aligned.m16n8k16.row.col.f32.bf16.bf16.f32 "
        "{%0,%1,%2,%3}, {%4,%5,%6,%7}, {%8,%9}, {%0,%1,%2,%3};"
        : "+f"(c[0]), "+f"(c[1]), "+f"(c[2]), "+f"(c[3])
        : "r"(a0), "r"(a1), "r"(a2), "r"(a3), "r"(b0), "r"(b1));
}
__device__ __forceinline__ void ldsm_x4(uint32_t& r0, uint32_t& r1,
                                        uint32_t& r2, uint32_t& r3, uint32_t addr)
{
    asm volatile("ldmatrix.sync.aligned.m8n8.x4.shared.b16 {%0,%1,%2,%3}, [%4];"
        : "=r"(r0), "=r"(r1), "=r"(r2), "=r"(r3) : "r"(addr));
}
__device__ __forceinline__ void ldsm_x4_t(uint32_t& r0, uint32_t& r1,
                                          uint32_t& r2, uint32_t& r3, uint32_t addr)
{
    asm volatile("ldmatrix.sync.aligned.m8n8.x4.trans.shared.b16 {%0,%1,%2,%3}, [%4];"
        : "=r"(r0), "=r"(r1), "=r"(r2), "=r"(r3) : "r"(addr));
}
#define CPA16(saddr, gptr) \
    asm volatile("cp.async.cg.shared.global [%0], [%1], 16;" :: "r"(saddr), "l"(gptr))
#define CPA_COMMIT() asm volatile("cp.async.commit_group;")
#define CPA_WAIT2()  asm volatile("cp.async.wait_group 2;")

// ---------------------------------------------------------------------------
// BF16 MMA GEMM, 4-stage cp.async pipeline, ldmatrix fragment loads.
// C = alpha * A @ op(B); bf16 in, fp32 accum, bf16 (OUTBF) or fp32 out.
//   A: M x K row-major (lda). kchunk>0: K-concat of chunks (merge GEMM).
//   B: TRANSB ? N x K row-major : K x N row-major. bmod>0 -> B uses z%bmod.
//   CSKIP: triangular causal launch — gridDim.x = nTiles*(nTiles+1)/2,
//          (mt,nt) decoded from blockIdx.x. CKLIM: cap K at tile diagonal.
// Tiles 128x128x32, 8 warps, 64x32 warp tile, m16n8k16 fragments.
// ---------------------------------------------------------------------------
#define ASTRIDE 40            // bf16 elems per smem row (80B)
#define BSTRIDE 136           // k-major B row stride (272B)
#define AS_SZ  (128*ASTRIDE)  // 5120 bf16
#define STG_SZ (2*AS_SZ)      // 20 KB per stage
#define NSTG   4
#define GEMM_SMEM (NSTG*STG_SZ*(int)sizeof(bf16))   // 81920 B

template<bool TRANSB, bool CSKIP, bool CKLIM, bool OUTBF>
__global__ void __launch_bounds__(256, 2)
mma_gemm(const bf16* __restrict__ A, int lda, long long sA,
         const bf16* __restrict__ Bp, int ldb, long long sB, int bmod,
         void* __restrict__ Cv, int ldc, long long sC,
         int M, int N, int K, float alpha,
         int kchunk, long long schunk)
{
    extern __shared__ bf16 smdyn[];

    int m0, n0;
    if (CSKIP) {
        // triangular decode: blockIdx.x in [0, nt*(nt+1)/2)
        const int bx = blockIdx.x;
        int mt = (int)((sqrtf(8.f * bx + 1.f) - 1.f) * 0.5f);
        while ((mt + 1) * (mt + 2) / 2 <= bx) ++mt;
        while (mt * (mt + 1) / 2 > bx) --mt;
        const int nt = bx - mt * (mt + 1) / 2;
        m0 = mt * 128; n0 = nt * 128;
    } else {
        m0 = blockIdx.y * 128;
        n0 = blockIdx.x * 128;
    }

    const int z = blockIdx.z;
    A  += (long long)z * sA;
    Bp += (long long)(bmod ? (z % bmod) : z) * sB;

    int kend = K;
    if (CKLIM) { int ke = m0 + 128; kend = (ke < K) ? ke : K; }
    const int niter = kend >> 5;   // BK = 32

    const int tid  = threadIdx.x;
    const int wid  = tid >> 5;
    const int lane = tid & 31;
    const int gid  = lane >> 2;
    const int tig  = lane & 3;
    const int wm   = (wid & 1) * 64;
    const int wn   = (wid >> 1) * 32;

    // per-thread ldmatrix address components
    const int aRow = wm + (lane & 15);            // + mi*16
    const int aK   = (lane >> 4) << 3;            // + kk
    const int btN  = wn + (lane & 7) + ((lane >> 4) << 3);  // TRANSB: n row; + ni*8? (x4 covers ni, ni+1)
    const int btK  = ((lane >> 3) & 1) << 3;                // TRANSB: + kk
    const int bkK  = (lane & 7) + (((lane >> 3) & 1) << 3); // k-major: k row; + kk
    const int bkN  = wn + ((lane >> 4) << 3);               // k-major: + ni*8

    float acc[4][4][4];
    #pragma unroll
    for (int i = 0; i < 4; i++)
        #pragma unroll
        for (int j = 0; j < 4; j++)
            #pragma unroll
            for (int r = 0; r < 4; r++) acc[i][j][r] = 0.f;

    auto loadA = [&](int stg, int k0) {
        const bf16* Ab;
        if (kchunk) { int c = k0 / kchunk; Ab = A + (long long)c * schunk + (k0 - c * kchunk); }
        else        Ab = A + k0;
        bf16* as = smdyn + stg * STG_SZ;
        #pragma unroll
        for (int i = 0; i < 2; i++) {
            int idx = tid + i * 256;
            int r = idx >> 2, c8 = (idx & 3) << 3;
            uint32_t sa = (uint32_t)__cvta_generic_to_shared(&as[r * ASTRIDE + c8]);
            CPA16(sa, Ab + (long long)(m0 + r) * lda + c8);
        }
    };
    auto loadB = [&](int stg, int k0) {
        bf16* bs = smdyn + stg * STG_SZ + AS_SZ;
        if (TRANSB) {
            #pragma unroll
            for (int i = 0; i < 2; i++) {
                int idx = tid + i * 256;
                int r = idx >> 2, c8 = (idx & 3) << 3;
                uint32_t sa = (uint32_t)__cvta_generic_to_shared(&bs[r * ASTRIDE + c8]);
                CPA16(sa, Bp + (long long)(n0 + r) * ldb + k0 + c8);
            }
        } else {
            #pragma unroll
            for (int i = 0; i < 2; i++) {
                int idx = tid + i * 256;
                int r = idx >> 4, c8 = (idx & 15) << 3;
                uint32_t sa = (uint32_t)__cvta_generic_to_shared(&bs[r * BSTRIDE + c8]);
                CPA16(sa, Bp + (long long)(k0 + r) * ldb + n0 + c8);
            }
        }
    };

    // prologue: stages 0,1,2
    loadA(0, 0);       loadB(0, 0);       CPA_COMMIT();
    loadA(1, 1 << 5);  loadB(1, 1 << 5);  CPA_COMMIT();
    loadA(2, 2 << 5);  loadB(2, 2 << 5);  CPA_COMMIT();

    for (int it = 0; it < niter; ++it) {
        CPA_WAIT2();
        __syncthreads();
        const int ld = it + 3;
        if (ld < niter) { loadA(ld & 3, ld << 5); loadB(ld & 3, ld << 5); }
        CPA_COMMIT();

        const bf16* as = smdyn + (it & 3) * STG_SZ;
        const bf16* bs = as + AS_SZ;

        #pragma unroll
        for (int kk = 0; kk < 32; kk += 16) {
            uint32_t a[4][4];
            #pragma unroll
            for (int mi = 0; mi < 4; mi++) {
                uint32_t sa = (uint32_t)__cvta_generic_to_shared(
                    &as[(aRow + mi * 16) * ASTRIDE + kk + aK]);
                ldsm_x4(a[mi][0], a[mi][1], a[mi][2], a[mi][3], sa);
            }
            uint32_t b[4][2];
            #pragma unroll
            for (int ni = 0; ni < 4; ni += 2) {
                if (TRANSB) {
                    // x4 covers (ni, ni+1): m0/m1 = n rows ni*8.., k / k+8
                    uint32_t sa = (uint32_t)__cvta_generic_to_shared(
                        &bs[(btN + ni * 8) * ASTRIDE + kk + btK]);
                    ldsm_x4(b[ni][0], b[ni][1], b[ni + 1][0], b[ni + 1][1], sa);
                } else {
                    // k-major: trans load; m0/m1 = k rows kk../kk+8, n = ni*8
                    uint32_t sa = (uint32_t)__cvta_generic_to_shared(
                        &bs[(kk + bkK) * BSTRIDE + bkN + ni * 8]);
                    ldsm_x4_t(b[ni][0], b[ni][1], b[ni + 1][0], b[ni + 1][1], sa);
                }
            }
            #pragma unroll
            for (int mi = 0; mi < 4; mi++)
                #pragma unroll
                for (int ni = 0; ni < 4; ni++)
                    mma_bf16(acc[mi][ni], a[mi][0], a[mi][1], a[mi][2], a[mi][3],
                             b[ni][0], b[ni][1]);
        }
    }

    // epilogue
    #pragma unroll
    for (int mi = 0; mi < 4; mi++) {
        #pragma unroll
        for (int ni = 0; ni < 4; ni++) {
            const int rr = m0 + wm + mi * 16 + gid;
            const int cc = n0 + wn + ni * 8 + tig * 2;
            #pragma unroll
            for (int hh = 0; hh < 2; hh++) {
                long long idx = ((long long)z * sC) + (long long)(rr + hh * 8) * ldc + cc;
                float vx = alpha * acc[mi][ni][hh * 2 + 0];
                float vy = alpha * acc[mi][ni][hh * 2 + 1];
                if (OUTBF) {
                    __nv_bfloat162 v2;
                    v2.x = __float2bfloat16(vx);
                    v2.y = __float2bfloat16(vy);
                    *reinterpret_cast<__nv_bfloat162*>(&((bf16*)Cv)[idx]) = v2;
                } else {
                    float2 v; v.x = vx; v.y = vy;
                    *reinterpret_cast<float2*>(&((float*)Cv)[idx]) = v;
                }
            }
        }
    }
}

// ---------------------------------------------------------------------------
// fp32 -> bf16 conversion kernels (weights)
// ---------------------------------------------------------------------------
__device__ __forceinline__ void store_bf4(bf16* dst, float4 v) {
    __nv_bfloat162 lo, hi;
    lo.x = __float2bfloat16(v.x); lo.y = __float2bfloat16(v.y);
    hi.x = __float2bfloat16(v.z); hi.y = __float2bfloat16(v.w);
    *reinterpret_cast<__nv_bfloat162*>(dst)     = lo;
    *reinterpret_cast<__nv_bfloat162*>(dst + 2) = hi;
}

__global__ void cvt_bf16_kernel(const float* __restrict__ in,
                                bf16* __restrict__ out, int n4)
{
    int i = blockIdx.x * 256 + threadIdx.x;
    if (i < n4) store_bf4(out + (size_t)i * 4, reinterpret_cast<const float4*>(in)[i]);
}

__global__ void cvt_inter_kernel(const float* __restrict__ in,
                                 bf16* __restrict__ out, int which, int n4)
{
    const int q4 = DD * DD / 4;
    int i = blockIdx.x * 256 + threadIdx.x;
    if (i < n4) {
        int c = i / q4, rem = i - c * q4;
        store_bf4(out + ((size_t)(2 * c + which) * q4 + rem) * 4,
                  reinterpret_cast<const float4*>(in)[i]);
    }
}

// ---------------------------------------------------------------------------
// Causal softmax over bf16 rows of [nz][T][T]: one read + one write.
// ---------------------------------------------------------------------------
__global__ void __launch_bounds__(256)
softmax_causal_kernel(bf16* __restrict__ S)
{
    __shared__ float red[256];
    const int r = blockIdx.x;
    const int zb = r / TT, t = r % TT;
    bf16* row = S + (long long)zb * TT * TT + (long long)t * TT;
    const int valid = t + 1;
    const int tid = threadIdx.x;

    float v[4];
    #pragma unroll
    for (int j = 0; j < 4; j++) {
        int s = tid + j * 256;
        v[j] = (s < valid) ? __bfloat162float(row[s]) : -1e30f;
    }
    float mx = fmaxf(fmaxf(v[0], v[1]), fmaxf(v[2], v[3]));
    red[tid] = mx; __syncthreads();
    for (int o = 128; o > 0; o >>= 1) {
        if (tid < o) red[tid] = fmaxf(red[tid], red[tid + o]);
        __syncthreads();
    }
    mx = red[0]; __syncthreads();

    float sum = 0.f;
    #pragma unroll
    for (int j = 0; j < 4; j++) {
        int s = tid + j * 256;
        v[j] = (s < valid) ? expf(v[j] - mx) : 0.f;
        sum += v[j];
    }
    red[tid] = sum; __syncthreads();
    for (int o = 128; o > 0; o >>= 1) {
        if (tid < o) red[tid] += red[tid + o];
        __syncthreads();
    }
    const float inv = 1.f / red[0];

    #pragma unroll
    for (int j = 0; j < 4; j++) {
        int s = tid + j * 256;
        row[s] = __float2bfloat16(v[j] * inv);
    }
}

// ---------------------------------------------------------------------------
// Chamber 0 combine: v = softplus(sp0)*sigmoid(h.gw0+gb0)*(O-h)
// delta = bf16(v); seq = v; inb = bf16(h + v)
// ---------------------------------------------------------------------------
__global__ void __launch_bounds__(256)
combine_c0_kernel(const float* __restrict__ h, const bf16* __restrict__ O,
                  const float* __restrict__ gw, const float* __restrict__ gb,
                  const float* __restrict__ sp,
                  bf16* __restrict__ delta, float* __restrict__ seq,
                  bf16* __restrict__ inb)
{
    __shared__ float red[256];
    const int r = blockIdx.x;
    const long long base = (long long)r * DD;
    const int tid = threadIdx.x;

    float dot = 0.f;
    for (int d = tid; d < DD; d += 256) dot += h[base + d] * gw[d];
    red[tid] = dot; __syncthreads();
    for (int o = 128; o > 0; o >>= 1) {
        if (tid < o) red[tid] += red[tid + o];
        __syncthreads();
    }
    const float gate = 1.f / (1.f + expf(-(red[0] + gb[0])));
    const float s = sp[0];
    float coef = (s > 20.f) ? s : log1pf(expf(s));
    coef *= gate;

    for (int d = tid; d < DD; d += 256) {
        const float hv = h[base + d];
        const float v = coef * (__bfloat162float(O[base + d]) - hv);
        delta[base + d] = __float2bfloat16(v);
        seq[base + d] = v;
        inb[base + d] = __float2bfloat16(hv + v);
    }
}

// ---------------------------------------------------------------------------
// Parallel combine for chambers 1..6 (blockIdx.y = ch-1)
// ---------------------------------------------------------------------------
__global__ void __launch_bounds__(256)
combine_par6_kernel(const float* __restrict__ h, const bf16* __restrict__ o6,
                    const float* __restrict__ gw, const float* __restrict__ gb,
                    const float* __restrict__ sp, bf16* __restrict__ delta6)
{
    __shared__ float red[256];
    const int i  = blockIdx.y;
    const int r  = blockIdx.x;
    const long long base  = (long long)r * DD;
    const long long cbase = (long long)i * BT * DD + base;
    const int tid = threadIdx.x;
    const float* gwi = gw + (size_t)(i + 1) * DD;

    float dot = 0.f;
    for (int d = tid; d < DD; d += 256) dot += h[base + d] * gwi[d];
    red[tid] = dot; __syncthreads();
    for (int o = 128; o > 0; o >>= 1) {
        if (tid < o) red[tid] += red[tid + o];
        __syncthreads();
    }
    const float gate = 1.f / (1.f + expf(-(red[0] + gb[i + 1])));
    const float s = sp[i + 1];
    float coef = (s > 20.f) ? s : log1pf(expf(s));
    coef *= gate;

    for (int d = tid; d < DD; d += 256)
        delta6[cbase + d] = __float2bfloat16(
            coef * (__bfloat162float(o6[cbase + d]) - h[base + d]));
}

// ---------------------------------------------------------------------------
// Sequential combine: In = h + seq_old; seq += coef*(O - In);
// inb = bf16(h + seq_new)  (null on last iteration)
// ---------------------------------------------------------------------------
__global__ void __launch_bounds__(256)
combine_seq_kernel(const float* __restrict__ h, const bf16* __restrict__ O,
                   const float* __restrict__ gw, const float* __restrict__ gb,
                   const float* __restrict__ sp,
                   float* __restrict__ seq, bf16* __restrict__ inb)
{
    __shared__ float red[256];
    const int r = blockIdx.x;
    const long long base = (long long)r * DD;
    const int tid = threadIdx.x;

    float dot = 0.f;
    for (int d = tid; d < DD; d += 256)
        dot += (h[base + d] + seq[base + d]) * gw[d];
    red[tid] = dot; __syncthreads();
    for (int o = 128; o > 0; o >>= 1) {
        if (tid < o) red[tid] += red[tid + o];
        __syncthreads();
    }
    const float gate = 1.f / (1.f + expf(-(red[0] + gb[0])));
    const float s = sp[0];
    float coef = (s > 20.f) ? s : log1pf(expf(s));
    coef *= gate;

    for (int d = tid; d < DD; d += 256) {
        const float hv = h[base + d];
        const float In = hv + seq[base + d];
        const float sv = seq[base + d] + coef * (__bfloat162float(O[base + d]) - In);
        seq[base + d] = sv;
        if (inb) inb[base + d] = __float2bfloat16(hv + sv);
    }
}

// ---------------------------------------------------------------------------
// LayerNorm: fp32 h + bf16 copy
// ---------------------------------------------------------------------------
__global__ void __launch_bounds__(256)
ln_kernel(const float* __restrict__ x, const float* __restrict__ g,
          const float* __restrict__ b, float* __restrict__ out,
          bf16* __restrict__ outb)
{
    __shared__ float r1[256], r2[256];
    const int r = blockIdx.x;
    const long long base = (long long)r * DD;
    const int tid = threadIdx.x;

    float s = 0.f, s2 = 0.f;
    for (int d = tid; d < DD; d += 256) {
        float v = x[base + d];
        s += v; s2 += v * v;
    }
    r1[tid] = s; r2[tid] = s2; __syncthreads();
    for (int o = 128; o > 0; o >>= 1) {
        if (tid < o) { r1[tid] += r1[tid + o]; r2[tid] += r2[tid + o]; }
        __syncthreads();
    }
    const float m   = r1[0] / DD;
    const float var = r2[0] / DD - m * m;
    const float inv = rsqrtf(var + 1e-5f);
    for (int d = tid; d < DD; d += 256) {
        float v = (x[base + d] - m) * inv * g[d] + b[d];
        out[base + d]  = v;
        outb[base + d] = __float2bfloat16(v);
    }
}

// ---------------------------------------------------------------------------
__global__ void __launch_bounds__(256)
final_kernel(const float* __restrict__ x, const float* __restrict__ seq,
             const float* __restrict__ par, const float* __restrict__ g,
             const float* __restrict__ b, const float* __restrict__ mode_logit,
             const float* __restrict__ res_gate, float* __restrict__ out)
{
    __shared__ float r1[256], r2[256];
    const int r = blockIdx.x;
    const long long base = (long long)r * DD;
    const int tid = threadIdx.x;

    const float mg = 1.f / (1.f + expf(-mode_logit[0]));
    const float rg = res_gate[0];

    float s = 0.f, s2 = 0.f;
    for (int d = tid; d < DD; d += 256) {
        float e = (1.f - mg) * seq[base + d] + mg * par[base + d];
        s += e; s2 += e * e;
    }
    r1[tid] = s; r2[tid] = s2; __syncthreads();
    for (int o = 128; o > 0; o >>= 1) {
        if (tid < o) { r1[tid] += r1[tid + o]; r2[tid] += r2[tid + o]; }
        __syncthreads();
    }
    const float m   = r1[0] / DD;
    const float var = r2[0] / DD - m * m;
    const float inv = rsqrtf(var + 1e-5f);
    for (int d = tid; d < DD; d += 256) {
        float e  = (1.f - mg) * seq[base + d] + mg * par[base + d];
        float ln = (e - m) * inv * g[d] + b[d];
        out[base + d] = x[base + d] + rg * ln;
    }
}

// ---------------------------------------------------------------------------
extern "C" void kernel_launch(void* const* d_in, const int* in_sizes, int n_in,
                              void* d_out, int out_size)
{
    const float* x             = (const float*)d_in[0];
    const float* Wq            = (const float*)d_in[1];
    const float* Wk            = (const float*)d_in[2];
    const float* gate_w        = (const float*)d_in[3];
    const float* gate_b        = (const float*)d_in[4];
    const float* scale_p       = (const float*)d_in[5];
    const float* merge_W       = (const float*)d_in[6];
    const float* mode_logit    = (const float*)d_in[7];
    const float* residual_gate = (const float*)d_in[8];
    const float* ln_pre_g      = (const float*)d_in[9];
    const float* ln_pre_b      = (const float*)d_in[10];
    const float* ln_post_g     = (const float*)d_in[11];
    const float* ln_post_b     = (const float*)d_in[12];
    float* out = (float*)d_out;

    float *h, *seq, *par;
    bf16 *hb, *inb, *q, *k, *o, *dl, *S, *qk2, *o2, *S2, *wqk, *mw;
    cudaGetSymbolAddress((void**)&h,   g_h);
    cudaGetSymbolAddress((void**)&seq, g_seq);
    cudaGetSymbolAddress((void**)&par, g_par);
    cudaGetSymbolAddress((void**)&hb,  g_hb);
    cudaGetSymbolAddress((void**)&inb, g_in);
    cudaGetSymbolAddress((void**)&q,   g_q);
    cudaGetSymbolAddress((void**)&k,   g_k);
    cudaGetSymbolAddress((void**)&o,   g_o);
    cudaGetSymbolAddress((void**)&dl,  g_d);
    cudaGetSymbolAddress((void**)&S,   g_S);
    cudaGetSymbolAddress((void**)&qk2, g_qk2);
    cudaGetSymbolAddress((void**)&o2,  g_o2);
    cudaGetSymbolAddress((void**)&S2,  g_S2);
    cudaGetSymbolAddress((void**)&wqk, g_wqk);
    cudaGetSymbolAddress((void**)&mw,  g_mw);

    static cudaStream_t s1 = nullptr;
    static cudaEvent_t evF1 = nullptr, evF2 = nullptr, evJ = nullptr;
    if (!s1) {
        cudaStreamCreateWithFlags(&s1, cudaStreamNonBlocking);
        cudaEventCreateWithFlags(&evF1, cudaEventDisableTiming);
        cudaEventCreateWithFlags(&evF2, cudaEventDisableTiming);
        cudaEventCreateWithFlags(&evJ,  cudaEventDisableTiming);
        cudaFuncSetAttribute(mma_gemm<false, false, false, true >,
                             cudaFuncAttributeMaxDynamicSharedMemorySize, GEMM_SMEM);
        cudaFuncSetAttribute(mma_gemm<true,  true,  false, true >,
                             cudaFuncAttributeMaxDynamicSharedMemorySize, GEMM_SMEM);
        cudaFuncSetAttribute(mma_gemm<false, false, true,  true >,
                             cudaFuncAttributeMaxDynamicSharedMemorySize, GEMM_SMEM);
        cudaFuncSetAttribute(mma_gemm<true,  false, false, false>,
                             cudaFuncAttributeMaxDynamicSharedMemorySize, GEMM_SMEM);
    }

    const float isd = 1.f / sqrtf((float)DD);
    const long long sQK  = (long long)DD * DD;
    const long long sRow = (long long)BT * DD;
    const long long sBT  = (long long)TT * DD;
    const long long sS   = (long long)TT * TT;
    const int wn4 = NCH * DD * DD / 4;
    const int NTRI = (TT / 128) * (TT / 128 + 1) / 2;   // 36 causal tiles
    bf16* q2 = qk2;
    bf16* k2 = qk2 + sRow;

    // -------- weight conversion (interleaved q|k) + pre-LN ------------------
    cvt_inter_kernel<<<(wn4 + 255) / 256, 256>>>(Wq, wqk, 0, wn4);
    cvt_inter_kernel<<<(wn4 + 255) / 256, 256>>>(Wk, wqk, 1, wn4);
    ln_kernel<<<BT, 256>>>(x, ln_pre_g, ln_pre_b, h, hb);

    // -------- fork: s1 runs parallel chambers 1..6 + merge weight cvt ------
    cudaEventRecord(evF1, 0);
    cudaStreamWaitEvent(s1, evF1, 0);

    cvt_bf16_kernel<<<(wn4 + 255) / 256, 256, 0, s1>>>(merge_W, mw, wn4);
    mma_gemm<false, false, false, true><<<dim3(6, 32, 6), 256, GEMM_SMEM, s1>>>(
        hb, DD, 0, wqk + 2 * sQK, DD, 2 * sQK, 0, q + sRow, DD, sRow, BT, DD, DD, 1.f, 0, 0);
    mma_gemm<false, false, false, true><<<dim3(6, 32, 6), 256, GEMM_SMEM, s1>>>(
        hb, DD, 0, wqk + 3 * sQK, DD, 2 * sQK, 0, k + sRow, DD, sRow, BT, DD, DD, 1.f, 0, 0);
    mma_gemm<true, true, false, true><<<dim3(NTRI, 1, 24), 256, GEMM_SMEM, s1>>>(
        q + sRow, DD, sBT, k + sRow, DD, sBT, 0, S, TT, sS, TT, TT, DD, isd, 0, 0);
    softmax_causal_kernel<<<24 * TT, 256, 0, s1>>>(S);
    mma_gemm<false, false, true, true><<<dim3(6, 8, 24), 256, GEMM_SMEM, s1>>>(
        S, TT, sS, hb, DD, sBT, BB, o + sRow, DD, sBT, TT, DD, TT, 1.f, 0, 0);
    combine_par6_kernel<<<dim3(BT, 6), 256, 0, s1>>>(
        h, o + sRow, gate_w, gate_b, scale_p, dl + sRow);

    // -------- chamber 0 on stream 0 (fused Q|K launch, z=2) -----------------
    mma_gemm<false, false, false, true><<<dim3(6, 32, 2), 256, GEMM_SMEM>>>(
        hb, DD, 0, wqk, DD, sQK, 0, qk2, DD, sRow, BT, DD, DD, 1.f, 0, 0);
    mma_gemm<true, true, false, true><<<dim3(NTRI, 1, BB), 256, GEMM_SMEM>>>(
        q2, DD, sBT, k2, DD, sBT, 0, S2, TT, sS, TT, TT, DD, isd, 0, 0);
    softmax_causal_kernel<<<BB * TT, 256>>>(S2);
    mma_gemm<false, false, true, true><<<dim3(6, 8, BB), 256, GEMM_SMEM>>>(
        S2, TT, sS, hb, DD, sBT, 0, o2, DD, sBT, TT, DD, TT, 1.f, 0, 0);
    combine_c0_kernel<<<BT, 256>>>(h, o2, gate_w, gate_b, scale_p, dl, seq, inb);

    // delta_0 ready -> merge GEMM on s1
    cudaEventRecord(evF2, 0);
    cudaStreamWaitEvent(s1, evF2, 0);
    mma_gemm<true, false, false, false><<<dim3(6, 32, 1), 256, GEMM_SMEM, s1>>>(
        dl, DD, 0, mw, NCH * DD, 0, 0, par, DD, 0,
        BT, DD, NCH * DD, 1.f, DD, sRow);
    cudaEventRecord(evJ, s1);

    // -------- sequential chambers 1..6 on stream 0 -------------------------
    for (int i = 1; i < NCH; i++) {
        mma_gemm<false, false, false, true><<<dim3(6, 32, 2), 256, GEMM_SMEM>>>(
            inb, DD, 0, wqk + (size_t)i * 2 * sQK, DD, sQK, 0,
            qk2, DD, sRow, BT, DD, DD, 1.f, 0, 0);
        mma_gemm<true, true, false, true><<<dim3(NTRI, 1, BB), 256, GEMM_SMEM>>>(
            q2, DD, sBT, k2, DD, sBT, 0, S2, TT, sS, TT, TT, DD, isd, 0, 0);
        softmax_causal_kernel<<<BB * TT, 256>>>(S2);
        mma_gemm<false, false, true, true><<<dim3(6, 8, BB), 256, GEMM_SMEM>>>(
            S2, TT, sS, inb, DD, sBT, 0, o2, DD, sBT, TT, DD, TT, 1.f, 0, 0);
        combine_seq_kernel<<<BT, 256>>>(h, o2, gate_w + (size_t)i * DD,
                                        gate_b + i, scale_p + i, seq,
                                        (i + 1 < NCH) ? inb : nullptr);
    }

    // -------- join + finalize ----------------------------------------------
    cudaStreamWaitEvent(0, evJ, 0);
    final_kernel<<<BT, 256>>>(x, seq, par, ln_post_g, ln_post_b,
                              mode_logit, residual_gate, out);
}

// round 15
// speedup vs baseline: 2.0826x; 1.0823x over previous
#include <cuda_runtime.h>
#include <cuda_bf16.h>
#include <stdint.h>
#include <math.h>

// Problem constants
#define BB  4
#define TT  1024
#define DD  768
#define NCH 7
#define BT  (BB*TT)   // 4096 rows

typedef __nv_bfloat16 bf16;

// ---------------------------------------------------------------------------
// Scratch (device globals; no allocation in kernel_launch)
// ---------------------------------------------------------------------------
__device__ float g_h   [(size_t)BT*DD];            // fp32 LN output
__device__ float g_seq [(size_t)BT*DD];
__device__ float g_par [(size_t)BT*DD];
__device__ bf16  g_hb  [(size_t)BT*DD];            // bf16 GEMM operand copy of h
__device__ bf16  g_in  [(size_t)BT*DD];            // bf16 (h+seq) GEMM operand
__device__ float g_cfP [(size_t)NCH*BT];           // parallel gates coef[ch][row]
__device__ float g_cfS [(size_t)BT];               // sequential gate coef[row]
// parallel branch (chambers 1..6 in slots 1..6)
__device__ bf16  g_q   [(size_t)NCH*BT*DD];
__device__ bf16  g_k   [(size_t)NCH*BT*DD];
__device__ bf16  g_d   [(size_t)NCH*BT*DD];
__device__ bf16  g_S   [(size_t)NCH*BB*TT*TT];
// sequential-branch private buffers
__device__ bf16  g_qk2 [(size_t)2*BT*DD];
__device__ bf16  g_S2  [(size_t)BB*TT*TT];
// bf16 weights: interleaved [chamber][q|k][D][D], plus merge
__device__ bf16  g_wqk [(size_t)NCH*2*DD*DD];
__device__ bf16  g_mw  [(size_t)DD*NCH*DD];

// ---------------------------------------------------------------------------
// MMA / LDSM helpers
// ---------------------------------------------------------------------------
__device__ __forceinline__ void mma_bf16(float c[4],
    uint32_t a0, uint32_t a1, uint32_t a2, uint32_t a3,
    uint32_t b0, uint32_t b1)
{
    asm volatile(
        "mma.sync.aligned.m16n8k16.row.col.f32.bf16.bf16.f32 "
        "{%0,%1,%2,%3}, {%4,%5,%6,%7}, {%8,%9}, {%0,%1,%2,%3};"
        : "+f"(c[0]), "+f"(c[1]), "+f"(c[2]), "+f"(c[3])
        : "r"(a0), "r"(a1), "r"(a2), "r"(a3), "r"(b0), "r"(b1));
}
__device__ __forceinline__ void ldsm_x4(uint32_t& r0, uint32_t& r1,
                                        uint32_t& r2, uint32_t& r3, uint32_t addr)
{
    asm volatile("ldmatrix.sync.aligned.m8n8.x4.shared.b16 {%0,%1,%2,%3}, [%4];"
        : "=r"(r0), "=r"(r1), "=r"(r2), "=r"(r3) : "r"(addr));
}
__device__ __forceinline__ void ldsm_x4_t(uint32_t& r0, uint32_t& r1,
                                          uint32_t& r2, uint32_t& r3, uint32_t addr)
{
    asm volatile("ldmatrix.sync.aligned.m8n8.x4.trans.shared.b16 {%0,%1,%2,%3}, [%4];"
        : "=r"(r0), "=r"(r1), "=r"(r2), "=r"(r3) : "r"(addr));
}
#define CPA16(saddr, gptr) \
    asm volatile("cp.async.cg.shared.global [%0], [%1], 16;" :: "r"(saddr), "l"(gptr))
#define CPA_COMMIT() asm volatile("cp.async.commit_group;")
#define CPA_WAIT2()  asm volatile("cp.async.wait_group 2;")

// ---------------------------------------------------------------------------
// BF16 MMA GEMM, 4-stage cp.async pipeline, ldmatrix fragment loads.
// EPI = fused epilogue variant:
//   0: C = alpha*A@op(B)  (bf16 if OUTBF else fp32)
//   1: parallel delta:  dout[R,c] = bf16(coef[R]*(acc - h[hrow,c]))
//   2: sequential seq:  old=seq; In=h+old; sv=old+coef*(acc-In); seq=sv;
//                       inb = bf16(h+sv) if inb != null
//   3: chamber0:        v=coef*(acc-h); dout=bf16(v); seq=v; inb=bf16(h+v)
// For EPI>0: R = z*TT + rr (coef/seq/delta/inb row); hrow = (z%BB)*TT+rr for
// EPI==1 else R. alpha must be 1 for EPI>0 semantics to match.
//   CSKIP: triangular causal launch. CKLIM: cap K at tile diagonal.
// Tiles 128x128x32, 8 warps, 64x32 warp tile, m16n8k16 fragments.
// ---------------------------------------------------------------------------
#define ASTRIDE 40
#define BSTRIDE 136
#define AS_SZ  (128*ASTRIDE)
#define STG_SZ (2*AS_SZ)
#define NSTG   4
#define GEMM_SMEM (NSTG*STG_SZ*(int)sizeof(bf16))   // 81920 B

template<bool TRANSB, bool CSKIP, bool CKLIM, bool OUTBF, int EPI>
__global__ void __launch_bounds__(256, 2)
mma_gemm(const bf16* __restrict__ A, int lda, long long sA,
         const bf16* __restrict__ Bp, int ldb, long long sB, int bmod,
         void* __restrict__ Cv, int ldc, long long sC,
         int M, int N, int K, float alpha,
         int kchunk, long long schunk,
         const float* __restrict__ coef, const float* __restrict__ hf,
         float* __restrict__ seqf, bf16* __restrict__ dout,
         bf16* __restrict__ inbb)
{
    extern __shared__ bf16 smdyn[];

    int m0, n0;
    if (CSKIP) {
        const int bx = blockIdx.x;
        int mt = (int)((sqrtf(8.f * bx + 1.f) - 1.f) * 0.5f);
        while ((mt + 1) * (mt + 2) / 2 <= bx) ++mt;
        while (mt * (mt + 1) / 2 > bx) --mt;
        const int nt = bx - mt * (mt + 1) / 2;
        m0 = mt * 128; n0 = nt * 128;
    } else {
        m0 = blockIdx.y * 128;
        n0 = blockIdx.x * 128;
    }

    const int z = blockIdx.z;
    A  += (long long)z * sA;
    Bp += (long long)(bmod ? (z % bmod) : z) * sB;

    int kend = K;
    if (CKLIM) { int ke = m0 + 128; kend = (ke < K) ? ke : K; }
    const int niter = kend >> 5;

    const int tid  = threadIdx.x;
    const int wid  = tid >> 5;
    const int lane = tid & 31;
    const int gid  = lane >> 2;
    const int tig  = lane & 3;
    const int wm   = (wid & 1) * 64;
    const int wn   = (wid >> 1) * 32;

    const int aRow = wm + (lane & 15);
    const int aK   = (lane >> 4) << 3;
    const int btN  = wn + (lane & 7) + ((lane >> 4) << 3);
    const int btK  = ((lane >> 3) & 1) << 3;
    const int bkK  = (lane & 7) + (((lane >> 3) & 1) << 3);
    const int bkN  = wn + ((lane >> 4) << 3);

    float acc[4][4][4];
    #pragma unroll
    for (int i = 0; i < 4; i++)
        #pragma unroll
        for (int j = 0; j < 4; j++)
            #pragma unroll
            for (int r = 0; r < 4; r++) acc[i][j][r] = 0.f;

    auto loadA = [&](int stg, int k0) {
        const bf16* Ab;
        if (kchunk) { int c = k0 / kchunk; Ab = A + (long long)c * schunk + (k0 - c * kchunk); }
        else        Ab = A + k0;
        bf16* as = smdyn + stg * STG_SZ;
        #pragma unroll
        for (int i = 0; i < 2; i++) {
            int idx = tid + i * 256;
            int r = idx >> 2, c8 = (idx & 3) << 3;
            uint32_t sa = (uint32_t)__cvta_generic_to_shared(&as[r * ASTRIDE + c8]);
            CPA16(sa, Ab + (long long)(m0 + r) * lda + c8);
        }
    };
    auto loadB = [&](int stg, int k0) {
        bf16* bs = smdyn + stg * STG_SZ + AS_SZ;
        if (TRANSB) {
            #pragma unroll
            for (int i = 0; i < 2; i++) {
                int idx = tid + i * 256;
                int r = idx >> 2, c8 = (idx & 3) << 3;
                uint32_t sa = (uint32_t)__cvta_generic_to_shared(&bs[r * ASTRIDE + c8]);
                CPA16(sa, Bp + (long long)(n0 + r) * ldb + k0 + c8);
            }
        } else {
            #pragma unroll
            for (int i = 0; i < 2; i++) {
                int idx = tid + i * 256;
                int r = idx >> 4, c8 = (idx & 15) << 3;
                uint32_t sa = (uint32_t)__cvta_generic_to_shared(&bs[r * BSTRIDE + c8]);
                CPA16(sa, Bp + (long long)(k0 + r) * ldb + n0 + c8);
            }
        }
    };

    loadA(0, 0);       loadB(0, 0);       CPA_COMMIT();
    loadA(1, 1 << 5);  loadB(1, 1 << 5);  CPA_COMMIT();
    loadA(2, 2 << 5);  loadB(2, 2 << 5);  CPA_COMMIT();

    for (int it = 0; it < niter; ++it) {
        CPA_WAIT2();
        __syncthreads();
        const int ld = it + 3;
        if (ld < niter) { loadA(ld & 3, ld << 5); loadB(ld & 3, ld << 5); }
        CPA_COMMIT();

        const bf16* as = smdyn + (it & 3) * STG_SZ;
        const bf16* bs = as + AS_SZ;

        #pragma unroll
        for (int kk = 0; kk < 32; kk += 16) {
            uint32_t a[4][4];
            #pragma unroll
            for (int mi = 0; mi < 4; mi++) {
                uint32_t sa = (uint32_t)__cvta_generic_to_shared(
                    &as[(aRow + mi * 16) * ASTRIDE + kk + aK]);
                ldsm_x4(a[mi][0], a[mi][1], a[mi][2], a[mi][3], sa);
            }
            uint32_t b[4][2];
            #pragma unroll
            for (int ni = 0; ni < 4; ni += 2) {
                if (TRANSB) {
                    uint32_t sa = (uint32_t)__cvta_generic_to_shared(
                        &bs[(btN + ni * 8) * ASTRIDE + kk + btK]);
                    ldsm_x4(b[ni][0], b[ni][1], b[ni + 1][0], b[ni + 1][1], sa);
                } else {
                    uint32_t sa = (uint32_t)__cvta_generic_to_shared(
                        &bs[(kk + bkK) * BSTRIDE + bkN + ni * 8]);
                    ldsm_x4_t(b[ni][0], b[ni][1], b[ni + 1][0], b[ni + 1][1], sa);
                }
            }
            #pragma unroll
            for (int mi = 0; mi < 4; mi++)
                #pragma unroll
                for (int ni = 0; ni < 4; ni++)
                    mma_bf16(acc[mi][ni], a[mi][0], a[mi][1], a[mi][2], a[mi][3],
                             b[ni][0], b[ni][1]);
        }
    }

    // epilogue
    #pragma unroll
    for (int mi = 0; mi < 4; mi++) {
        #pragma unroll
        for (int ni = 0; ni < 4; ni++) {
            const int rr = m0 + wm + mi * 16 + gid;
            const int cc = n0 + wn + ni * 8 + tig * 2;
            #pragma unroll
            for (int hh = 0; hh < 2; hh++) {
                const int r = rr + hh * 8;
                float a0 = alpha * acc[mi][ni][hh * 2 + 0];
                float a1 = alpha * acc[mi][ni][hh * 2 + 1];
                if (EPI == 0) {
                    long long idx = (long long)z * sC + (long long)r * ldc + cc;
                    if (OUTBF) {
                        __nv_bfloat162 v2;
                        v2.x = __float2bfloat16(a0);
                        v2.y = __float2bfloat16(a1);
                        *reinterpret_cast<__nv_bfloat162*>(&((bf16*)Cv)[idx]) = v2;
                    } else {
                        float2 v; v.x = a0; v.y = a1;
                        *reinterpret_cast<float2*>(&((float*)Cv)[idx]) = v;
                    }
                } else {
                    const long long R = (long long)z * TT + r;
                    const long long hrow = (EPI == 1) ? ((long long)(z & (BB - 1)) * TT + r) : R;
                    const float cf = coef[R];
                    const long long hix = hrow * DD + cc;
                    const long long eix = R * DD + cc;
                    const float h0 = hf[hix], h1 = hf[hix + 1];
                    if (EPI == 1) {
                        __nv_bfloat162 v2;
                        v2.x = __float2bfloat16(cf * (a0 - h0));
                        v2.y = __float2bfloat16(cf * (a1 - h1));
                        *reinterpret_cast<__nv_bfloat162*>(&dout[eix]) = v2;
                    } else if (EPI == 2) {
                        float2 o2v = *reinterpret_cast<const float2*>(&seqf[eix]);
                        float sv0 = o2v.x + cf * (a0 - (h0 + o2v.x));
                        float sv1 = o2v.y + cf * (a1 - (h1 + o2v.y));
                        float2 s2; s2.x = sv0; s2.y = sv1;
                        *reinterpret_cast<float2*>(&seqf[eix]) = s2;
                        if (inbb) {
                            __nv_bfloat162 v2;
                            v2.x = __float2bfloat16(h0 + sv0);
                            v2.y = __float2bfloat16(h1 + sv1);
                            *reinterpret_cast<__nv_bfloat162*>(&inbb[eix]) = v2;
                        }
                    } else {  // EPI == 3
                        float v0 = cf * (a0 - h0), v1 = cf * (a1 - h1);
                        __nv_bfloat162 d2;
                        d2.x = __float2bfloat16(v0); d2.y = __float2bfloat16(v1);
                        *reinterpret_cast<__nv_bfloat162*>(&dout[eix]) = d2;
                        float2 s2; s2.x = v0; s2.y = v1;
                        *reinterpret_cast<float2*>(&seqf[eix]) = s2;
                        __nv_bfloat162 i2;
                        i2.x = __float2bfloat16(h0 + v0); i2.y = __float2bfloat16(h1 + v1);
                        *reinterpret_cast<__nv_bfloat162*>(&inbb[eix]) = i2;
                    }
                }
            }
        }
    }
}

// ---------------------------------------------------------------------------
// fp32 -> bf16 conversion kernels (weights)
// ---------------------------------------------------------------------------
__device__ __forceinline__ void store_bf4(bf16* dst, float4 v) {
    __nv_bfloat162 lo, hi;
    lo.x = __float2bfloat16(v.x); lo.y = __float2bfloat16(v.y);
    hi.x = __float2bfloat16(v.z); hi.y = __float2bfloat16(v.w);
    *reinterpret_cast<__nv_bfloat162*>(dst)     = lo;
    *reinterpret_cast<__nv_bfloat162*>(dst + 2) = hi;
}

__global__ void cvt_bf16_kernel(const float* __restrict__ in,
                                bf16* __restrict__ out, int n4)
{
    int i = blockIdx.x * 256 + threadIdx.x;
    if (i < n4) store_bf4(out + (size_t)i * 4, reinterpret_cast<const float4*>(in)[i]);
}

__global__ void cvt_inter_kernel(const float* __restrict__ in,
                                 bf16* __restrict__ out, int which, int n4)
{
    const int q4 = DD * DD / 4;
    int i = blockIdx.x * 256 + threadIdx.x;
    if (i < n4) {
        int c = i / q4, rem = i - c * q4;
        store_bf4(out + ((size_t)(2 * c + which) * q4 + rem) * 4,
                  reinterpret_cast<const float4*>(in)[i]);
    }
}

// ---------------------------------------------------------------------------
// Gate precompute, parallel branch: coefP[ch][row] for all 7 chambers from h.
// One block per row; warp w handles chamber w (warp 7 idle).
// ---------------------------------------------------------------------------
__global__ void __launch_bounds__(256)
gate_par_kernel(const float* __restrict__ h, const float* __restrict__ gw,
                const float* __restrict__ gb, const float* __restrict__ sp,
                float* __restrict__ coefP)
{
    const int r = blockIdx.x;
    const int w = threadIdx.x >> 5;
    const int lane = threadIdx.x & 31;
    if (w >= NCH) return;
    const float* hr = h + (long long)r * DD;
    const float* g  = gw + (size_t)w * DD;
    float dot = 0.f;
    for (int d = lane; d < DD; d += 32) dot += hr[d] * g[d];
    #pragma unroll
    for (int o = 16; o > 0; o >>= 1) dot += __shfl_xor_sync(0xffffffffu, dot, o);
    if (lane == 0) {
        const float gate = 1.f / (1.f + expf(-(dot + gb[w])));
        const float s = sp[w];
        float c = (s > 20.f) ? s : log1pf(expf(s));
        coefP[(size_t)w * BT + r] = c * gate;
    }
}

// ---------------------------------------------------------------------------
// Gate precompute, sequential: coefS[row] from (h+seq).gw + gb. Warp per row.
// ---------------------------------------------------------------------------
__global__ void __launch_bounds__(256)
gate_seq_kernel(const float* __restrict__ h, const float* __restrict__ seq,
                const float* __restrict__ gw, const float* __restrict__ gb,
                const float* __restrict__ sp, float* __restrict__ coefS)
{
    const int r = blockIdx.x * 8 + (threadIdx.x >> 5);
    const int lane = threadIdx.x & 31;
    const long long base = (long long)r * DD;
    float dot = 0.f;
    for (int d = lane; d < DD; d += 32)
        dot += (h[base + d] + seq[base + d]) * gw[d];
    #pragma unroll
    for (int o = 16; o > 0; o >>= 1) dot += __shfl_xor_sync(0xffffffffu, dot, o);
    if (lane == 0) {
        const float gate = 1.f / (1.f + expf(-(dot + gb[0])));
        const float s = sp[0];
        float c = (s > 20.f) ? s : log1pf(expf(s));
        coefS[r] = c * gate;
    }
}

// ---------------------------------------------------------------------------
// Causal softmax, warp-per-row (8 rows/block, no block barriers).
// Zeros written for s > t (PV reads up to the 128 tile boundary).
// ---------------------------------------------------------------------------
__global__ void __launch_bounds__(256)
softmax_causal_kernel(bf16* __restrict__ S)
{
    const int r = blockIdx.x * 8 + (threadIdx.x >> 5);
    const int lane = threadIdx.x & 31;
    const int zb = r >> 10, t = r & (TT - 1);
    bf16* row = S + (long long)zb * TT * TT + (long long)t * TT;
    const int valid = t + 1;

    float v[32];
    #pragma unroll
    for (int j = 0; j < 32; j++) {
        int s = lane + j * 32;
        v[j] = (s < valid) ? __bfloat162float(row[s]) : -1e30f;
    }
    float mx = -1e30f;
    #pragma unroll
    for (int j = 0; j < 32; j++) mx = fmaxf(mx, v[j]);
    #pragma unroll
    for (int o = 16; o > 0; o >>= 1) mx = fmaxf(mx, __shfl_xor_sync(0xffffffffu, mx, o));

    float sum = 0.f;
    #pragma unroll
    for (int j = 0; j < 32; j++) {
        int s = lane + j * 32;
        v[j] = (s < valid) ? expf(v[j] - mx) : 0.f;
        sum += v[j];
    }
    #pragma unroll
    for (int o = 16; o > 0; o >>= 1) sum += __shfl_xor_sync(0xffffffffu, sum, o);
    const float inv = 1.f / sum;

    #pragma unroll
    for (int j = 0; j < 32; j++)
        row[lane + j * 32] = __float2bfloat16(v[j] * inv);
}

// ---------------------------------------------------------------------------
// LayerNorm: fp32 h + bf16 copy
// ---------------------------------------------------------------------------
__global__ void __launch_bounds__(256)
ln_kernel(const float* __restrict__ x, const float* __restrict__ g,
          const float* __restrict__ b, float* __restrict__ out,
          bf16* __restrict__ outb)
{
    __shared__ float r1[256], r2[256];
    const int r = blockIdx.x;
    const long long base = (long long)r * DD;
    const int tid = threadIdx.x;

    float s = 0.f, s2 = 0.f;
    for (int d = tid; d < DD; d += 256) {
        float v = x[base + d];
        s += v; s2 += v * v;
    }
    r1[tid] = s; r2[tid] = s2; __syncthreads();
    for (int o = 128; o > 0; o >>= 1) {
        if (tid < o) { r1[tid] += r1[tid + o]; r2[tid] += r2[tid + o]; }
        __syncthreads();
    }
    const float m   = r1[0] / DD;
    const float var = r2[0] / DD - m * m;
    const float inv = rsqrtf(var + 1e-5f);
    for (int d = tid; d < DD; d += 256) {
        float v = (x[base + d] - m) * inv * g[d] + b[d];
        out[base + d]  = v;
        outb[base + d] = __float2bfloat16(v);
    }
}

// ---------------------------------------------------------------------------
__global__ void __launch_bounds__(256)
final_kernel(const float* __restrict__ x, const float* __restrict__ seq,
             const float* __restrict__ par, const float* __restrict__ g,
             const float* __restrict__ b, const float* __restrict__ mode_logit,
             const float* __restrict__ res_gate, float* __restrict__ out)
{
    __shared__ float r1[256], r2[256];
    const int r = blockIdx.x;
    const long long base = (long long)r * DD;
    const int tid = threadIdx.x;

    const float mg = 1.f / (1.f + expf(-mode_logit[0]));
    const float rg = res_gate[0];

    float s = 0.f, s2 = 0.f;
    for (int d = tid; d < DD; d += 256) {
        float e = (1.f - mg) * seq[base + d] + mg * par[base + d];
        s += e; s2 += e * e;
    }
    r1[tid] = s; r2[tid] = s2; __syncthreads();
    for (int o = 128; o > 0; o >>= 1) {
        if (tid < o) { r1[tid] += r1[tid + o]; r2[tid] += r2[tid + o]; }
        __syncthreads();
    }
    const float m   = r1[0] / DD;
    const float var = r2[0] / DD - m * m;
    const float inv = rsqrtf(var + 1e-5f);
    for (int d = tid; d < DD; d += 256) {
        float e  = (1.f - mg) * seq[base + d] + mg * par[base + d];
        float ln = (e - m) * inv * g[d] + b[d];
        out[base + d] = x[base + d] + rg * ln;
    }
}

// ---------------------------------------------------------------------------
extern "C" void kernel_launch(void* const* d_in, const int* in_sizes, int n_in,
                              void* d_out, int out_size)
{
    const float* x             = (const float*)d_in[0];
    const float* Wq            = (const float*)d_in[1];
    const float* Wk            = (const float*)d_in[2];
    const float* gate_w        = (const float*)d_in[3];
    const float* gate_b        = (const float*)d_in[4];
    const float* scale_p       = (const float*)d_in[5];
    const float* merge_W       = (const float*)d_in[6];
    const float* mode_logit    = (const float*)d_in[7];
    const float* residual_gate = (const float*)d_in[8];
    const float* ln_pre_g      = (const float*)d_in[9];
    const float* ln_pre_b      = (const float*)d_in[10];
    const float* ln_post_g     = (const float*)d_in[11];
    const float* ln_post_b     = (const float*)d_in[12];
    float* out = (float*)d_out;

    float *h, *seq, *par, *cfP, *cfS;
    bf16 *hb, *inb, *q, *k, *dl, *S, *qk2, *S2, *wqk, *mw;
    cudaGetSymbolAddress((void**)&h,   g_h);
    cudaGetSymbolAddress((void**)&seq, g_seq);
    cudaGetSymbolAddress((void**)&par, g_par);
    cudaGetSymbolAddress((void**)&cfP, g_cfP);
    cudaGetSymbolAddress((void**)&cfS, g_cfS);
    cudaGetSymbolAddress((void**)&hb,  g_hb);
    cudaGetSymbolAddress((void**)&inb, g_in);
    cudaGetSymbolAddress((void**)&q,   g_q);
    cudaGetSymbolAddress((void**)&k,   g_k);
    cudaGetSymbolAddress((void**)&dl,  g_d);
    cudaGetSymbolAddress((void**)&S,   g_S);
    cudaGetSymbolAddress((void**)&qk2, g_qk2);
    cudaGetSymbolAddress((void**)&S2,  g_S2);
    cudaGetSymbolAddress((void**)&wqk, g_wqk);
    cudaGetSymbolAddress((void**)&mw,  g_mw);

    static cudaStream_t s1 = nullptr;
    static cudaEvent_t evF1 = nullptr, evF2 = nullptr, evJ = nullptr;
    if (!s1) {
        cudaStreamCreateWithFlags(&s1, cudaStreamNonBlocking);
        cudaEventCreateWithFlags(&evF1, cudaEventDisableTiming);
        cudaEventCreateWithFlags(&evF2, cudaEventDisableTiming);
        cudaEventCreateWithFlags(&evJ,  cudaEventDisableTiming);
        cudaFuncSetAttribute(mma_gemm<false, false, false, true,  0>,   // proj
                             cudaFuncAttributeMaxDynamicSharedMemorySize, GEMM_SMEM);
        cudaFuncSetAttribute(mma_gemm<true,  true,  false, true,  0>,   // QK^T
                             cudaFuncAttributeMaxDynamicSharedMemorySize, GEMM_SMEM);
        cudaFuncSetAttribute(mma_gemm<false, false, true,  true,  1>,   // PV par
                             cudaFuncAttributeMaxDynamicSharedMemorySize, GEMM_SMEM);
        cudaFuncSetAttribute(mma_gemm<false, false, true,  true,  2>,   // PV seq
                             cudaFuncAttributeMaxDynamicSharedMemorySize, GEMM_SMEM);
        cudaFuncSetAttribute(mma_gemm<false, false, true,  true,  3>,   // PV c0
                             cudaFuncAttributeMaxDynamicSharedMemorySize, GEMM_SMEM);
        cudaFuncSetAttribute(mma_gemm<true,  false, false, false, 0>,   // merge
                             cudaFuncAttributeMaxDynamicSharedMemorySize, GEMM_SMEM);
    }

    const float isd = 1.f / sqrtf((float)DD);
    const long long sQK  = (long long)DD * DD;
    const long long sRow = (long long)BT * DD;
    const long long sBT  = (long long)TT * DD;
    const long long sS   = (long long)TT * TT;
    const int wn4 = NCH * DD * DD / 4;
    const int NTRI = (TT / 128) * (TT / 128 + 1) / 2;   // 36 causal tiles
    bf16* q2 = qk2;
    bf16* k2 = qk2 + sRow;

    // -------- weight conversion + pre-LN + all parallel gates ---------------
    cvt_inter_kernel<<<(wn4 + 255) / 256, 256>>>(Wq, wqk, 0, wn4);
    cvt_inter_kernel<<<(wn4 + 255) / 256, 256>>>(Wk, wqk, 1, wn4);
    ln_kernel<<<BT, 256>>>(x, ln_pre_g, ln_pre_b, h, hb);
    gate_par_kernel<<<BT, 256>>>(h, gate_w, gate_b, scale_p, cfP);

    // -------- fork: s1 runs parallel chambers 1..6 + merge weight cvt ------
    cudaEventRecord(evF1, 0);
    cudaStreamWaitEvent(s1, evF1, 0);

    cvt_bf16_kernel<<<(wn4 + 255) / 256, 256, 0, s1>>>(merge_W, mw, wn4);
    mma_gemm<false, false, false, true, 0><<<dim3(6, 32, 6), 256, GEMM_SMEM, s1>>>(
        hb, DD, 0, wqk + 2 * sQK, DD, 2 * sQK, 0, q + sRow, DD, sRow, BT, DD, DD, 1.f,
        0, 0, nullptr, nullptr, nullptr, nullptr, nullptr);
    mma_gemm<false, false, false, true, 0><<<dim3(6, 32, 6), 256, GEMM_SMEM, s1>>>(
        hb, DD, 0, wqk + 3 * sQK, DD, 2 * sQK, 0, k + sRow, DD, sRow, BT, DD, DD, 1.f,
        0, 0, nullptr, nullptr, nullptr, nullptr, nullptr);
    mma_gemm<true, true, false, true, 0><<<dim3(NTRI, 1, 24), 256, GEMM_SMEM, s1>>>(
        q + sRow, DD, sBT, k + sRow, DD, sBT, 0, S, TT, sS, TT, TT, DD, isd,
        0, 0, nullptr, nullptr, nullptr, nullptr, nullptr);
    softmax_causal_kernel<<<24 * TT / 8, 256, 0, s1>>>(S);
    // PV + fused parallel combine: delta_ch = coef*(O - h)
    mma_gemm<false, false, true, true, 1><<<dim3(6, 8, 24), 256, GEMM_SMEM, s1>>>(
        S, TT, sS, hb, DD, sBT, BB, nullptr, DD, 0, TT, DD, TT, 1.f,
        0, 0, cfP + BT, h, nullptr, dl + sRow, nullptr);

    // -------- chamber 0 on stream 0 (fused Q|K, PV+combine EPI=3) -----------
    mma_gemm<false, false, false, true, 0><<<dim3(6, 32, 2), 256, GEMM_SMEM>>>(
        hb, DD, 0, wqk, DD, sQK, 0, qk2, DD, sRow, BT, DD, DD, 1.f,
        0, 0, nullptr, nullptr, nullptr, nullptr, nullptr);
    mma_gemm<true, true, false, true, 0><<<dim3(NTRI, 1, BB), 256, GEMM_SMEM>>>(
        q2, DD, sBT, k2, DD, sBT, 0, S2, TT, sS, TT, TT, DD, isd,
        0, 0, nullptr, nullptr, nullptr, nullptr, nullptr);
    softmax_causal_kernel<<<BB * TT / 8, 256>>>(S2);
    mma_gemm<false, false, true, true, 3><<<dim3(6, 8, BB), 256, GEMM_SMEM>>>(
        S2, TT, sS, hb, DD, sBT, 0, nullptr, DD, 0, TT, DD, TT, 1.f,
        0, 0, cfP, h, seq, dl, inb);

    // delta_0 ready -> merge GEMM on s1
    cudaEventRecord(evF2, 0);
    cudaStreamWaitEvent(s1, evF2, 0);
    mma_gemm<true, false, false, false, 0><<<dim3(6, 32, 1), 256, GEMM_SMEM, s1>>>(
        dl, DD, 0, mw, NCH * DD, 0, 0, par, DD, 0, BT, DD, NCH * DD, 1.f,
        DD, sRow, nullptr, nullptr, nullptr, nullptr, nullptr);
    cudaEventRecord(evJ, s1);

    // -------- sequential chambers 1..6 on stream 0 -------------------------
    for (int i = 1; i < NCH; i++) {
        gate_seq_kernel<<<BT / 8, 256>>>(h, seq, gate_w + (size_t)i * DD,
                                         gate_b + i, scale_p + i, cfS);
        mma_gemm<false, false, false, true, 0><<<dim3(6, 32, 2), 256, GEMM_SMEM>>>(
            inb, DD, 0, wqk + (size_t)i * 2 * sQK, DD, sQK, 0,
            qk2, DD, sRow, BT, DD, DD, 1.f,
            0, 0, nullptr, nullptr, nullptr, nullptr, nullptr);
        mma_gemm<true, true, false, true, 0><<<dim3(NTRI, 1, BB), 256, GEMM_SMEM>>>(
            q2, DD, sBT, k2, DD, sBT, 0, S2, TT, sS, TT, TT, DD, isd,
            0, 0, nullptr, nullptr, nullptr, nullptr, nullptr);
        softmax_causal_kernel<<<BB * TT / 8, 256>>>(S2);
        mma_gemm<false, false, true, true, 2><<<dim3(6, 8, BB), 256, GEMM_SMEM>>>(
            S2, TT, sS, inb, DD, sBT, 0, nullptr, DD, 0, TT, DD, TT, 1.f,
            0, 0, cfS, h, seq, nullptr, (i + 1 < NCH) ? inb : nullptr);
    }

    // -------- join + finalize ----------------------------------------------
    cudaStreamWaitEvent(0, evJ, 0);
    final_kernel<<<BT, 256>>>(x, seq, par, ln_post_g, ln_post_b,
                              mode_logit, residual_gate, out);
}

// round 16
// speedup vs baseline: 2.3885x; 1.1469x over previous
#include <cuda_runtime.h>
#include <cuda_bf16.h>
#include <stdint.h>
#include <math.h>

// Problem constants
#define BB  4
#define TT  1024
#define DD  768
#define NCH 7
#define BT  (BB*TT)   // 4096 rows

typedef __nv_bfloat16 bf16;

// ---------------------------------------------------------------------------
// Scratch (device globals; no allocation in kernel_launch)
// ---------------------------------------------------------------------------
__device__ float g_h   [(size_t)BT*DD];            // fp32 LN output
__device__ float g_seq [(size_t)BT*DD];
__device__ float g_par [(size_t)BT*DD];
__device__ bf16  g_hb  [(size_t)BT*DD];            // bf16 GEMM operand copy of h
__device__ bf16  g_in  [(size_t)BT*DD];            // bf16 (h+seq) GEMM operand
__device__ float g_cfP [(size_t)NCH*BT];           // parallel gates coef[ch][row]
__device__ float g_cfS [(size_t)BT];               // sequential gate coef[row]
// parallel branch (chambers 1..6 in slots 1..6)
__device__ bf16  g_q   [(size_t)NCH*BT*DD];        // p = In @ G
__device__ bf16  g_d   [(size_t)NCH*BT*DD];
__device__ bf16  g_S   [(size_t)NCH*BB*TT*TT];
// sequential-branch private buffers
__device__ bf16  g_q2  [(size_t)BT*DD];
__device__ bf16  g_S2  [(size_t)BB*TT*TT];
// bf16 weights: interleaved [chamber][q|k][D][D], merge, and G = Wq Wk^T
__device__ bf16  g_wqk [(size_t)NCH*2*DD*DD];
__device__ bf16  g_mw  [(size_t)DD*NCH*DD];
__device__ bf16  g_G   [(size_t)NCH*DD*DD];

// ---------------------------------------------------------------------------
// MMA / LDSM helpers
// ---------------------------------------------------------------------------
__device__ __forceinline__ void mma_bf16(float c[4],
    uint32_t a0, uint32_t a1, uint32_t a2, uint32_t a3,
    uint32_t b0, uint32_t b1)
{
    asm volatile(
        "mma.sync.aligned.m16n8k16.row.col.f32.bf16.bf16.f32 "
        "{%0,%1,%2,%3}, {%4,%5,%6,%7}, {%8,%9}, {%0,%1,%2,%3};"
        : "+f"(c[0]), "+f"(c[1]), "+f"(c[2]), "+f"(c[3])
        : "r"(a0), "r"(a1), "r"(a2), "r"(a3), "r"(b0), "r"(b1));
}
__device__ __forceinline__ void ldsm_x4(uint32_t& r0, uint32_t& r1,
                                        uint32_t& r2, uint32_t& r3, uint32_t addr)
{
    asm volatile("ldmatrix.sync.aligned.m8n8.x4.shared.b16 {%0,%1,%2,%3}, [%4];"
        : "=r"(r0), "=r"(r1), "=r"(r2), "=r"(r3) : "r"(addr));
}
__device__ __forceinline__ void ldsm_x4_t(uint32_t& r0, uint32_t& r1,
                                          uint32_t& r2, uint32_t& r3, uint32_t addr)
{
    asm volatile("ldmatrix.sync.aligned.m8n8.x4.trans.shared.b16 {%0,%1,%2,%3}, [%4];"
        : "=r"(r0), "=r"(r1), "=r"(r2), "=r"(r3) : "r"(addr));
}
#define CPA16(saddr, gptr) \
    asm volatile("cp.async.cg.shared.global [%0], [%1], 16;" :: "r"(saddr), "l"(gptr))
#define CPA_COMMIT() asm volatile("cp.async.commit_group;")
#define CPA_WAIT2()  asm volatile("cp.async.wait_group 2;")

// ---------------------------------------------------------------------------
// BF16 MMA GEMM, 4-stage cp.async pipeline, ldmatrix fragment loads.
// EPI variants: 0 plain C; 1 parallel delta; 2 sequential seq update; 3 c0.
// (see R14/15 comments; semantics unchanged)
// ---------------------------------------------------------------------------
#define ASTRIDE 40
#define BSTRIDE 136
#define AS_SZ  (128*ASTRIDE)
#define STG_SZ (2*AS_SZ)
#define NSTG   4
#define GEMM_SMEM (NSTG*STG_SZ*(int)sizeof(bf16))   // 81920 B

template<bool TRANSB, bool CSKIP, bool CKLIM, bool OUTBF, int EPI>
__global__ void __launch_bounds__(256, 2)
mma_gemm(const bf16* __restrict__ A, int lda, long long sA,
         const bf16* __restrict__ Bp, int ldb, long long sB, int bmod,
         void* __restrict__ Cv, int ldc, long long sC,
         int M, int N, int K, float alpha,
         int kchunk, long long schunk,
         const float* __restrict__ coef, const float* __restrict__ hf,
         float* __restrict__ seqf, bf16* __restrict__ dout,
         bf16* __restrict__ inbb)
{
    extern __shared__ bf16 smdyn[];

    int m0, n0;
    if (CSKIP) {
        const int bx = blockIdx.x;
        int mt = (int)((sqrtf(8.f * bx + 1.f) - 1.f) * 0.5f);
        while ((mt + 1) * (mt + 2) / 2 <= bx) ++mt;
        while (mt * (mt + 1) / 2 > bx) --mt;
        const int nt = bx - mt * (mt + 1) / 2;
        m0 = mt * 128; n0 = nt * 128;
    } else {
        m0 = blockIdx.y * 128;
        n0 = blockIdx.x * 128;
    }

    const int z = blockIdx.z;
    A  += (long long)z * sA;
    Bp += (long long)(bmod ? (z % bmod) : z) * sB;

    int kend = K;
    if (CKLIM) { int ke = m0 + 128; kend = (ke < K) ? ke : K; }
    const int niter = kend >> 5;

    const int tid  = threadIdx.x;
    const int wid  = tid >> 5;
    const int lane = tid & 31;
    const int gid  = lane >> 2;
    const int tig  = lane & 3;
    const int wm   = (wid & 1) * 64;
    const int wn   = (wid >> 1) * 32;

    const int aRow = wm + (lane & 15);
    const int aK   = (lane >> 4) << 3;
    const int btN  = wn + (lane & 7) + ((lane >> 4) << 3);
    const int btK  = ((lane >> 3) & 1) << 3;
    const int bkK  = (lane & 7) + (((lane >> 3) & 1) << 3);
    const int bkN  = wn + ((lane >> 4) << 3);

    float acc[4][4][4];
    #pragma unroll
    for (int i = 0; i < 4; i++)
        #pragma unroll
        for (int j = 0; j < 4; j++)
            #pragma unroll
            for (int r = 0; r < 4; r++) acc[i][j][r] = 0.f;

    auto loadA = [&](int stg, int k0) {
        const bf16* Ab;
        if (kchunk) { int c = k0 / kchunk; Ab = A + (long long)c * schunk + (k0 - c * kchunk); }
        else        Ab = A + k0;
        bf16* as = smdyn + stg * STG_SZ;
        #pragma unroll
        for (int i = 0; i < 2; i++) {
            int idx = tid + i * 256;
            int r = idx >> 2, c8 = (idx & 3) << 3;
            uint32_t sa = (uint32_t)__cvta_generic_to_shared(&as[r * ASTRIDE + c8]);
            CPA16(sa, Ab + (long long)(m0 + r) * lda + c8);
        }
    };
    auto loadB = [&](int stg, int k0) {
        bf16* bs = smdyn + stg * STG_SZ + AS_SZ;
        if (TRANSB) {
            #pragma unroll
            for (int i = 0; i < 2; i++) {
                int idx = tid + i * 256;
                int r = idx >> 2, c8 = (idx & 3) << 3;
                uint32_t sa = (uint32_t)__cvta_generic_to_shared(&bs[r * ASTRIDE + c8]);
                CPA16(sa, Bp + (long long)(n0 + r) * ldb + k0 + c8);
            }
        } else {
            #pragma unroll
            for (int i = 0; i < 2; i++) {
                int idx = tid + i * 256;
                int r = idx >> 4, c8 = (idx & 15) << 3;
                uint32_t sa = (uint32_t)__cvta_generic_to_shared(&bs[r * BSTRIDE + c8]);
                CPA16(sa, Bp + (long long)(k0 + r) * ldb + n0 + c8);
            }
        }
    };

    loadA(0, 0);       loadB(0, 0);       CPA_COMMIT();
    loadA(1, 1 << 5);  loadB(1, 1 << 5);  CPA_COMMIT();
    loadA(2, 2 << 5);  loadB(2, 2 << 5);  CPA_COMMIT();

    for (int it = 0; it < niter; ++it) {
        CPA_WAIT2();
        __syncthreads();
        const int ld = it + 3;
        if (ld < niter) { loadA(ld & 3, ld << 5); loadB(ld & 3, ld << 5); }
        CPA_COMMIT();

        const bf16* as = smdyn + (it & 3) * STG_SZ;
        const bf16* bs = as + AS_SZ;

        #pragma unroll
        for (int kk = 0; kk < 32; kk += 16) {
            uint32_t a[4][4];
            #pragma unroll
            for (int mi = 0; mi < 4; mi++) {
                uint32_t sa = (uint32_t)__cvta_generic_to_shared(
                    &as[(aRow + mi * 16) * ASTRIDE + kk + aK]);
                ldsm_x4(a[mi][0], a[mi][1], a[mi][2], a[mi][3], sa);
            }
            uint32_t b[4][2];
            #pragma unroll
            for (int ni = 0; ni < 4; ni += 2) {
                if (TRANSB) {
                    uint32_t sa = (uint32_t)__cvta_generic_to_shared(
                        &bs[(btN + ni * 8) * ASTRIDE + kk + btK]);
                    ldsm_x4(b[ni][0], b[ni][1], b[ni + 1][0], b[ni + 1][1], sa);
                } else {
                    uint32_t sa = (uint32_t)__cvta_generic_to_shared(
                        &bs[(kk + bkK) * BSTRIDE + bkN + ni * 8]);
                    ldsm_x4_t(b[ni][0], b[ni][1], b[ni + 1][0], b[ni + 1][1], sa);
                }
            }
            #pragma unroll
            for (int mi = 0; mi < 4; mi++)
                #pragma unroll
                for (int ni = 0; ni < 4; ni++)
                    mma_bf16(acc[mi][ni], a[mi][0], a[mi][1], a[mi][2], a[mi][3],
                             b[ni][0], b[ni][1]);
        }
    }

    // epilogue
    #pragma unroll
    for (int mi = 0; mi < 4; mi++) {
        #pragma unroll
        for (int ni = 0; ni < 4; ni++) {
            const int rr = m0 + wm + mi * 16 + gid;
            const int cc = n0 + wn + ni * 8 + tig * 2;
            #pragma unroll
            for (int hh = 0; hh < 2; hh++) {
                const int r = rr + hh * 8;
                float a0 = alpha * acc[mi][ni][hh * 2 + 0];
                float a1 = alpha * acc[mi][ni][hh * 2 + 1];
                if (EPI == 0) {
                    long long idx = (long long)z * sC + (long long)r * ldc + cc;
                    if (OUTBF) {
                        __nv_bfloat162 v2;
                        v2.x = __float2bfloat16(a0);
                        v2.y = __float2bfloat16(a1);
                        *reinterpret_cast<__nv_bfloat162*>(&((bf16*)Cv)[idx]) = v2;
                    } else {
                        float2 v; v.x = a0; v.y = a1;
                        *reinterpret_cast<float2*>(&((float*)Cv)[idx]) = v;
                    }
                } else {
                    const long long R = (long long)z * TT + r;
                    const long long hrow = (EPI == 1) ? ((long long)(z & (BB - 1)) * TT + r) : R;
                    const float cf = coef[R];
                    const long long hix = hrow * DD + cc;
                    const long long eix = R * DD + cc;
                    const float h0 = hf[hix], h1 = hf[hix + 1];
                    if (EPI == 1) {
                        __nv_bfloat162 v2;
                        v2.x = __float2bfloat16(cf * (a0 - h0));
                        v2.y = __float2bfloat16(cf * (a1 - h1));
                        *reinterpret_cast<__nv_bfloat162*>(&dout[eix]) = v2;
                    } else if (EPI == 2) {
                        float2 o2v = *reinterpret_cast<const float2*>(&seqf[eix]);
                        float sv0 = o2v.x + cf * (a0 - (h0 + o2v.x));
                        float sv1 = o2v.y + cf * (a1 - (h1 + o2v.y));
                        float2 s2; s2.x = sv0; s2.y = sv1;
                        *reinterpret_cast<float2*>(&seqf[eix]) = s2;
                        if (inbb) {
                            __nv_bfloat162 v2;
                            v2.x = __float2bfloat16(h0 + sv0);
                            v2.y = __float2bfloat16(h1 + sv1);
                            *reinterpret_cast<__nv_bfloat162*>(&inbb[eix]) = v2;
                        }
                    } else {  // EPI == 3
                        float v0 = cf * (a0 - h0), v1 = cf * (a1 - h1);
                        __nv_bfloat162 d2;
                        d2.x = __float2bfloat16(v0); d2.y = __float2bfloat16(v1);
                        *reinterpret_cast<__nv_bfloat162*>(&dout[eix]) = d2;
                        float2 s2; s2.x = v0; s2.y = v1;
                        *reinterpret_cast<float2*>(&seqf[eix]) = s2;
                        __nv_bfloat162 i2;
                        i2.x = __float2bfloat16(h0 + v0); i2.y = __float2bfloat16(h1 + v1);
                        *reinterpret_cast<__nv_bfloat162*>(&inbb[eix]) = i2;
                    }
                }
            }
        }
    }
}

// ---------------------------------------------------------------------------
// fp32 -> bf16 conversion kernels (weights)
// ---------------------------------------------------------------------------
__device__ __forceinline__ void store_bf4(bf16* dst, float4 v) {
    __nv_bfloat162 lo, hi;
    lo.x = __float2bfloat16(v.x); lo.y = __float2bfloat16(v.y);
    hi.x = __float2bfloat16(v.z); hi.y = __float2bfloat16(v.w);
    *reinterpret_cast<__nv_bfloat162*>(dst)     = lo;
    *reinterpret_cast<__nv_bfloat162*>(dst + 2) = hi;
}

__global__ void cvt_bf16_kernel(const float* __restrict__ in,
                                bf16* __restrict__ out, int n4)
{
    int i = blockIdx.x * 256 + threadIdx.x;
    if (i < n4) store_bf4(out + (size_t)i * 4, reinterpret_cast<const float4*>(in)[i]);
}

__global__ void cvt_inter_kernel(const float* __restrict__ in,
                                 bf16* __restrict__ out, int which, int n4)
{
    const int q4 = DD * DD / 4;
    int i = blockIdx.x * 256 + threadIdx.x;
    if (i < n4) {
        int c = i / q4, rem = i - c * q4;
        store_bf4(out + ((size_t)(2 * c + which) * q4 + rem) * 4,
                  reinterpret_cast<const float4*>(in)[i]);
    }
}

// ---------------------------------------------------------------------------
// Gate precompute, parallel branch: stage h row in smem once, 7 warp-dots.
// ---------------------------------------------------------------------------
__global__ void __launch_bounds__(256)
gate_par_kernel(const float* __restrict__ h, const float* __restrict__ gw,
                const float* __restrict__ gb, const float* __restrict__ sp,
                float* __restrict__ coefP)
{
    __shared__ float hs[DD];
    const int r = blockIdx.x;
    const int tid = threadIdx.x;
    const float* hr = h + (long long)r * DD;
    for (int d = tid; d < DD; d += 256) hs[d] = hr[d];
    __syncthreads();

    const int w = tid >> 5;
    const int lane = tid & 31;
    if (w >= NCH) return;
    const float* g = gw + (size_t)w * DD;
    float dot = 0.f;
    for (int d = lane; d < DD; d += 32) dot += hs[d] * g[d];
    #pragma unroll
    for (int o = 16; o > 0; o >>= 1) dot += __shfl_xor_sync(0xffffffffu, dot, o);
    if (lane == 0) {
        const float gate = 1.f / (1.f + expf(-(dot + gb[w])));
        const float s = sp[w];
        float c = (s > 20.f) ? s : log1pf(expf(s));
        coefP[(size_t)w * BT + r] = c * gate;
    }
}

// ---------------------------------------------------------------------------
// Gate precompute, sequential: coefS[row] from (h+seq).gw + gb. Warp per row.
// ---------------------------------------------------------------------------
__global__ void __launch_bounds__(256)
gate_seq_kernel(const float* __restrict__ h, const float* __restrict__ seq,
                const float* __restrict__ gw, const float* __restrict__ gb,
                const float* __restrict__ sp, float* __restrict__ coefS)
{
    const int r = blockIdx.x * 8 + (threadIdx.x >> 5);
    const int lane = threadIdx.x & 31;
    const long long base = (long long)r * DD;
    float dot = 0.f;
    for (int d = lane; d < DD; d += 32)
        dot += (h[base + d] + seq[base + d]) * gw[d];
    #pragma unroll
    for (int o = 16; o > 0; o >>= 1) dot += __shfl_xor_sync(0xffffffffu, dot, o);
    if (lane == 0) {
        const float gate = 1.f / (1.f + expf(-(dot + gb[0])));
        const float s = sp[0];
        float c = (s > 20.f) ? s : log1pf(expf(s));
        coefS[r] = c * gate;
    }
}

// ---------------------------------------------------------------------------
// Causal softmax, warp-per-row (8 rows/block, no block barriers).
// ---------------------------------------------------------------------------
__global__ void __launch_bounds__(256)
softmax_causal_kernel(bf16* __restrict__ S)
{
    const int r = blockIdx.x * 8 + (threadIdx.x >> 5);
    const int lane = threadIdx.x & 31;
    const int zb = r >> 10, t = r & (TT - 1);
    bf16* row = S + (long long)zb * TT * TT + (long long)t * TT;
    const int valid = t + 1;

    float v[32];
    #pragma unroll
    for (int j = 0; j < 32; j++) {
        int s = lane + j * 32;
        v[j] = (s < valid) ? __bfloat162float(row[s]) : -1e30f;
    }
    float mx = -1e30f;
    #pragma unroll
    for (int j = 0; j < 32; j++) mx = fmaxf(mx, v[j]);
    #pragma unroll
    for (int o = 16; o > 0; o >>= 1) mx = fmaxf(mx, __shfl_xor_sync(0xffffffffu, mx, o));

    float sum = 0.f;
    #pragma unroll
    for (int j = 0; j < 32; j++) {
        int s = lane + j * 32;
        v[j] = (s < valid) ? expf(v[j] - mx) : 0.f;
        sum += v[j];
    }
    #pragma unroll
    for (int o = 16; o > 0; o >>= 1) sum += __shfl_xor_sync(0xffffffffu, sum, o);
    const float inv = 1.f / sum;

    #pragma unroll
    for (int j = 0; j < 32; j++)
        row[lane + j * 32] = __float2bfloat16(v[j] * inv);
}

// ---------------------------------------------------------------------------
// LayerNorm: fp32 h + bf16 copy
// ---------------------------------------------------------------------------
__global__ void __launch_bounds__(256)
ln_kernel(const float* __restrict__ x, const float* __restrict__ g,
          const float* __restrict__ b, float* __restrict__ out,
          bf16* __restrict__ outb)
{
    __shared__ float r1[256], r2[256];
    const int r = blockIdx.x;
    const long long base = (long long)r * DD;
    const int tid = threadIdx.x;

    float s = 0.f, s2 = 0.f;
    for (int d = tid; d < DD; d += 256) {
        float v = x[base + d];
        s += v; s2 += v * v;
    }
    r1[tid] = s; r2[tid] = s2; __syncthreads();
    for (int o = 128; o > 0; o >>= 1) {
        if (tid < o) { r1[tid] += r1[tid + o]; r2[tid] += r2[tid + o]; }
        __syncthreads();
    }
    const float m   = r1[0] / DD;
    const float var = r2[0] / DD - m * m;
    const float inv = rsqrtf(var + 1e-5f);
    for (int d = tid; d < DD; d += 256) {
        float v = (x[base + d] - m) * inv * g[d] + b[d];
        out[base + d]  = v;
        outb[base + d] = __float2bfloat16(v);
    }
}

// ---------------------------------------------------------------------------
__global__ void __launch_bounds__(256)
final_kernel(const float* __restrict__ x, const float* __restrict__ seq,
             const float* __restrict__ par, const float* __restrict__ g,
             const float* __restrict__ b, const float* __restrict__ mode_logit,
             const float* __restrict__ res_gate, float* __restrict__ out)
{
    __shared__ float r1[256], r2[256];
    const int r = blockIdx.x;
    const long long base = (long long)r * DD;
    const int tid = threadIdx.x;

    const float mg = 1.f / (1.f + expf(-mode_logit[0]));
    const float rg = res_gate[0];

    float s = 0.f, s2 = 0.f;
    for (int d = tid; d < DD; d += 256) {
        float e = (1.f - mg) * seq[base + d] + mg * par[base + d];
        s += e; s2 += e * e;
    }
    r1[tid] = s; r2[tid] = s2; __syncthreads();
    for (int o = 128; o > 0; o >>= 1) {
        if (tid < o) { r1[tid] += r1[tid + o]; r2[tid] += r2[tid + o]; }
        __syncthreads();
    }
    const float m   = r1[0] / DD;
    const float var = r2[0] / DD - m * m;
    const float inv = rsqrtf(var + 1e-5f);
    for (int d = tid; d < DD; d += 256) {
        float e  = (1.f - mg) * seq[base + d] + mg * par[base + d];
        float ln = (e - m) * inv * g[d] + b[d];
        out[base + d] = x[base + d] + rg * ln;
    }
}

// ---------------------------------------------------------------------------
extern "C" void kernel_launch(void* const* d_in, const int* in_sizes, int n_in,
                              void* d_out, int out_size)
{
    const float* x             = (const float*)d_in[0];
    const float* Wq            = (const float*)d_in[1];
    const float* Wk            = (const float*)d_in[2];
    const float* gate_w        = (const float*)d_in[3];
    const float* gate_b        = (const float*)d_in[4];
    const float* scale_p       = (const float*)d_in[5];
    const float* merge_W       = (const float*)d_in[6];
    const float* mode_logit    = (const float*)d_in[7];
    const float* residual_gate = (const float*)d_in[8];
    const float* ln_pre_g      = (const float*)d_in[9];
    const float* ln_pre_b      = (const float*)d_in[10];
    const float* ln_post_g     = (const float*)d_in[11];
    const float* ln_post_b     = (const float*)d_in[12];
    float* out = (float*)d_out;

    float *h, *seq, *par, *cfP, *cfS;
    bf16 *hb, *inb, *q, *dl, *S, *q2, *S2, *wqk, *mw, *G;
    cudaGetSymbolAddress((void**)&h,   g_h);
    cudaGetSymbolAddress((void**)&seq, g_seq);
    cudaGetSymbolAddress((void**)&par, g_par);
    cudaGetSymbolAddress((void**)&cfP, g_cfP);
    cudaGetSymbolAddress((void**)&cfS, g_cfS);
    cudaGetSymbolAddress((void**)&hb,  g_hb);
    cudaGetSymbolAddress((void**)&inb, g_in);
    cudaGetSymbolAddress((void**)&q,   g_q);
    cudaGetSymbolAddress((void**)&dl,  g_d);
    cudaGetSymbolAddress((void**)&S,   g_S);
    cudaGetSymbolAddress((void**)&q2,  g_q2);
    cudaGetSymbolAddress((void**)&S2,  g_S2);
    cudaGetSymbolAddress((void**)&wqk, g_wqk);
    cudaGetSymbolAddress((void**)&mw,  g_mw);
    cudaGetSymbolAddress((void**)&G,   g_G);

    static cudaStream_t s1 = nullptr, s2g = nullptr;
    static cudaEvent_t evF1 = nullptr, evF2 = nullptr, evJ = nullptr;
    static cudaEvent_t evA = nullptr, evB = nullptr;
    if (!s1) {
        cudaStreamCreateWithFlags(&s1,  cudaStreamNonBlocking);
        cudaStreamCreateWithFlags(&s2g, cudaStreamNonBlocking);
        cudaEventCreateWithFlags(&evF1, cudaEventDisableTiming);
        cudaEventCreateWithFlags(&evF2, cudaEventDisableTiming);
        cudaEventCreateWithFlags(&evJ,  cudaEventDisableTiming);
        cudaEventCreateWithFlags(&evA,  cudaEventDisableTiming);
        cudaEventCreateWithFlags(&evB,  cudaEventDisableTiming);
        cudaFuncSetAttribute(mma_gemm<false, false, false, true,  0>,   // proj
                             cudaFuncAttributeMaxDynamicSharedMemorySize, GEMM_SMEM);
        cudaFuncSetAttribute(mma_gemm<true,  false, false, true,  0>,   // G = Wq Wk^T
                             cudaFuncAttributeMaxDynamicSharedMemorySize, GEMM_SMEM);
        cudaFuncSetAttribute(mma_gemm<true,  true,  false, true,  0>,   // S = p In^T
                             cudaFuncAttributeMaxDynamicSharedMemorySize, GEMM_SMEM);
        cudaFuncSetAttribute(mma_gemm<false, false, true,  true,  1>,   // PV par
                             cudaFuncAttributeMaxDynamicSharedMemorySize, GEMM_SMEM);
        cudaFuncSetAttribute(mma_gemm<false, false, true,  true,  2>,   // PV seq
                             cudaFuncAttributeMaxDynamicSharedMemorySize, GEMM_SMEM);
        cudaFuncSetAttribute(mma_gemm<false, false, true,  true,  3>,   // PV c0
                             cudaFuncAttributeMaxDynamicSharedMemorySize, GEMM_SMEM);
        cudaFuncSetAttribute(mma_gemm<true,  false, false, false, 0>,   // merge
                             cudaFuncAttributeMaxDynamicSharedMemorySize, GEMM_SMEM);
    }

    const float isd = 1.f / sqrtf((float)DD);
    const long long sQK  = (long long)DD * DD;
    const long long sRow = (long long)BT * DD;
    const long long sBT  = (long long)TT * DD;
    const long long sS   = (long long)TT * TT;
    const int wn4 = NCH * DD * DD / 4;
    const int NTRI = (TT / 128) * (TT / 128 + 1) / 2;   // 36 causal tiles

    // -------- weight conversion + G + pre-LN + parallel gates ---------------
    cvt_inter_kernel<<<(wn4 + 255) / 256, 256>>>(Wq, wqk, 0, wn4);
    cvt_inter_kernel<<<(wn4 + 255) / 256, 256>>>(Wk, wqk, 1, wn4);
    ln_kernel<<<BT, 256>>>(x, ln_pre_g, ln_pre_b, h, hb);
    // G_i = Wq_i @ Wk_i^T  (TRANSB; A/B from interleaved wqk, stride 2*sQK)
    mma_gemm<true, false, false, true, 0><<<dim3(6, 6, NCH), 256, GEMM_SMEM>>>(
        wqk, DD, 2 * sQK, wqk + sQK, DD, 2 * sQK, 0, G, DD, sQK, DD, DD, DD, 1.f,
        0, 0, nullptr, nullptr, nullptr, nullptr, nullptr);
    gate_par_kernel<<<BT, 256>>>(h, gate_w, gate_b, scale_p, cfP);

    // -------- fork: s1 runs parallel chambers 1..6 + merge weight cvt ------
    cudaEventRecord(evF1, 0);
    cudaStreamWaitEvent(s1, evF1, 0);

    cvt_bf16_kernel<<<(wn4 + 255) / 256, 256, 0, s1>>>(merge_W, mw, wn4);
    // p_i = h @ G_i  (chambers 1..6, z=6; single projection GEMM)
    mma_gemm<false, false, false, true, 0><<<dim3(6, 32, 6), 256, GEMM_SMEM, s1>>>(
        hb, DD, 0, G + sQK, DD, sQK, 0, q + sRow, DD, sRow, BT, DD, DD, 1.f,
        0, 0, nullptr, nullptr, nullptr, nullptr, nullptr);
    // S = p @ h^T / sqrt(D)
    mma_gemm<true, true, false, true, 0><<<dim3(NTRI, 1, 24), 256, GEMM_SMEM, s1>>>(
        q + sRow, DD, sBT, hb, DD, sBT, BB, S, TT, sS, TT, TT, DD, isd,
        0, 0, nullptr, nullptr, nullptr, nullptr, nullptr);
    softmax_causal_kernel<<<24 * TT / 8, 256, 0, s1>>>(S);
    // PV + fused parallel combine
    mma_gemm<false, false, true, true, 1><<<dim3(6, 8, 24), 256, GEMM_SMEM, s1>>>(
        S, TT, sS, hb, DD, sBT, BB, nullptr, DD, 0, TT, DD, TT, 1.f,
        0, 0, cfP + BT, h, nullptr, dl + sRow, nullptr);

    // -------- chamber 0 on stream 0 ------------------------------------------
    mma_gemm<false, false, false, true, 0><<<dim3(6, 32, 1), 256, GEMM_SMEM>>>(
        hb, DD, 0, G, DD, 0, 0, q2, DD, 0, BT, DD, DD, 1.f,
        0, 0, nullptr, nullptr, nullptr, nullptr, nullptr);
    mma_gemm<true, true, false, true, 0><<<dim3(NTRI, 1, BB), 256, GEMM_SMEM>>>(
        q2, DD, sBT, hb, DD, sBT, 0, S2, TT, sS, TT, TT, DD, isd,
        0, 0, nullptr, nullptr, nullptr, nullptr, nullptr);
    softmax_causal_kernel<<<BB * TT / 8, 256>>>(S2);
    mma_gemm<false, false, true, true, 3><<<dim3(6, 8, BB), 256, GEMM_SMEM>>>(
        S2, TT, sS, hb, DD, sBT, 0, nullptr, DD, 0, TT, DD, TT, 1.f,
        0, 0, cfP, h, seq, dl, inb);

    // delta_0 ready -> merge GEMM on s1
    cudaEventRecord(evF2, 0);
    cudaStreamWaitEvent(s1, evF2, 0);
    mma_gemm<true, false, false, false, 0><<<dim3(6, 32, 1), 256, GEMM_SMEM, s1>>>(
        dl, DD, 0, mw, NCH * DD, 0, 0, par, DD, 0, BT, DD, NCH * DD, 1.f,
        DD, sRow, nullptr, nullptr, nullptr, nullptr, nullptr);
    cudaEventRecord(evJ, s1);

    // gate for iteration 1 off-chain on s2g (seq just written by c0 PV)
    cudaEventRecord(evA, 0);
    cudaStreamWaitEvent(s2g, evA, 0);
    gate_seq_kernel<<<BT / 8, 256, 0, s2g>>>(h, seq, gate_w + DD,
                                             gate_b + 1, scale_p + 1, cfS);
    cudaEventRecord(evB, s2g);

    // -------- sequential chambers 1..6 on stream 0 -------------------------
    for (int i = 1; i < NCH; i++) {
        // p = inb @ G_i   (one projection GEMM instead of two)
        mma_gemm<false, false, false, true, 0><<<dim3(6, 32, 1), 256, GEMM_SMEM>>>(
            inb, DD, 0, G + (size_t)i * sQK, DD, 0, 0, q2, DD, 0, BT, DD, DD, 1.f,
            0, 0, nullptr, nullptr, nullptr, nullptr, nullptr);
        // S = p @ inb^T / sqrt(D)
        mma_gemm<true, true, false, true, 0><<<dim3(NTRI, 1, BB), 256, GEMM_SMEM>>>(
            q2, DD, sBT, inb, DD, sBT, 0, S2, TT, sS, TT, TT, DD, isd,
            0, 0, nullptr, nullptr, nullptr, nullptr, nullptr);
        softmax_causal_kernel<<<BB * TT / 8, 256>>>(S2);
        cudaStreamWaitEvent(0, evB, 0);     // gate coef ready
        mma_gemm<false, false, true, true, 2><<<dim3(6, 8, BB), 256, GEMM_SMEM>>>(
            S2, TT, sS, inb, DD, sBT, 0, nullptr, DD, 0, TT, DD, TT, 1.f,
            0, 0, cfS, h, seq, nullptr, (i + 1 < NCH) ? inb : nullptr);
        if (i + 1 < NCH) {
            cudaEventRecord(evA, 0);
            cudaStreamWaitEvent(s2g, evA, 0);
            gate_seq_kernel<<<BT / 8, 256, 0, s2g>>>(h, seq,
                gate_w + (size_t)(i + 1) * DD, gate_b + i + 1,
                scale_p + i + 1, cfS);
            cudaEventRecord(evB, s2g);
        }
    }

    // -------- join + finalize ----------------------------------------------
    cudaStreamWaitEvent(0, evJ, 0);
    final_kernel<<<BT, 256>>>(x, seq, par, ln_post_g, ln_post_b,
                              mode_logit, residual_gate, out);
}